// round 1
// baseline (speedup 1.0000x reference)
#include <cuda_runtime.h>
#include <cstdint>

// ---------------- problem constants ----------------
#define C_CLS   201
#define K_PROT  5
#define DIM     768
#define B_IMG   64
#define NP      256            // patches per image
#define BN_TOT  (B_IMG*NP)     // 16384 rows
#define CK      (C_CLS*K_PROT) // 1005
#define EPSV    1e-12f

// output region sizes
#define SZ_PP   (BN_TOT*CK)          // 16,465,920
#define SZ_IMG  (B_IMG*CK)           // 64,320
#define SZ_CLS  (B_IMG*(C_CLS-1))    // 12,800
#define SZ_PART (BN_TOT)             // 16,384
#define SZ_NP   (C_CLS*K_PROT*DIM)   // 771,840
#define SZ_PL   (BN_TOT)             // 16,384

// ---------------- device scratch (static; no allocations) ----------------
__device__ float g_An[BN_TOT*DIM];          // normalized tokens   (50 MB)
__device__ float g_Bn[CK*DIM];              // normalized protos   (3 MB)
__device__ int   g_pl[BN_TOT];              // pseudo label per row
__device__ int   g_rowlist[C_CLS*BN_TOT];   // per-class row lists (13 MB)
__device__ int   g_count[C_CLS];            // rows per class
__device__ float g_Q[BN_TOT*K_PROT];        // Sinkhorn assignment per row
__device__ float g_Pacc[C_CLS*K_PROT*DIM];  // prototype candidate accumulator

// ---------------- small helpers ----------------
union F2 { float2 f; unsigned long long u; };

__device__ __forceinline__ void ffma2(F2& d, const F2& a, const F2& b) {
    asm("fma.rn.f32x2 %0, %1, %2, %0;" : "+l"(d.u) : "l"(a.u), "l"(b.u));
}

// ---------------- kernel 0: zero scratch ----------------
__global__ void zero_k() {
    int i = blockIdx.x * 256 + threadIdx.x;
    if (i < C_CLS*K_PROT*DIM) g_Pacc[i] = 0.0f;
    if (i < C_CLS)            g_count[i] = 0;
}

// ---------------- kernel 1/2: L2-normalize rows (warp per row) ----------------
template <int MODE>   // 0 -> tokens into g_An, 1 -> prototypes into g_Bn
__global__ void norm_rows(const float* __restrict__ in, int nrows) {
    int warp = (blockIdx.x * blockDim.x + threadIdx.x) >> 5;
    int lane = threadIdx.x & 31;
    if (warp >= nrows) return;
    const float4* ip = (const float4*)(in + (size_t)warp * DIM);
    float4* op = (float4*)((MODE == 0 ? g_An : g_Bn) + (size_t)warp * DIM);
    float4 v[6];
    float s = 0.0f;
#pragma unroll
    for (int j = 0; j < 6; j++) {
        v[j] = ip[lane + j*32];
        s += v[j].x*v[j].x + v[j].y*v[j].y + v[j].z*v[j].z + v[j].w*v[j].w;
    }
#pragma unroll
    for (int o = 16; o; o >>= 1) s += __shfl_xor_sync(0xffffffffu, s, o);
    float inv = 1.0f / (sqrtf(s) + EPSV);
#pragma unroll
    for (int j = 0; j < 6; j++) {
        float4 w = v[j];
        w.x *= inv; w.y *= inv; w.z *= inv; w.w *= inv;
        op[lane + j*32] = w;
    }
}

// ---------------- kernel 3: GEMM  L = An (16384x768) @ Bn^T (1005x768) ----------------
#define BM 128
#define BN 64
#define BK 16
#define ASTR 132
#define BSTR 68

__global__ void __launch_bounds__(256) gemm_nt(float* __restrict__ Cout) {
    __shared__ __align__(16) float As[BK*ASTR];
    __shared__ __align__(16) float Bs[BK*BSTR];

    int tid = threadIdx.x;
    int tx = tid & 15;          // N direction (16 * TN=4 = 64)
    int ty = tid >> 4;          // M direction (16 * TM=8 = 128)
    int row0 = blockIdx.y * BM;
    int col0 = blockIdx.x * BN;

    F2 acc[8][2];
#pragma unroll
    for (int i = 0; i < 8; i++) { acc[i][0].u = 0ull; acc[i][1].u = 0ull; }

    const float4* A4 = (const float4*)g_An;   // row stride 192 float4
    const float4* B4 = (const float4*)g_Bn;

    for (int k0 = 0; k0 < DIM; k0 += BK) {
        // load A tile (128 x 16), transposed into As[k][m]
#pragma unroll
        for (int i = 0; i < 2; i++) {
            int fi = tid + i*256;            // 0..511
            int fr = fi >> 2;                // row 0..127
            int fc = fi & 3;                 // float4 col 0..3
            float4 v = A4[(size_t)(row0 + fr)*192 + (k0 >> 2) + fc];
            As[(fc*4+0)*ASTR + fr] = v.x;
            As[(fc*4+1)*ASTR + fr] = v.y;
            As[(fc*4+2)*ASTR + fr] = v.z;
            As[(fc*4+3)*ASTR + fr] = v.w;
        }
        // load B tile (64 x 16), transposed into Bs[k][n]
        {
            int bn = tid >> 2;               // 0..63
            int fc = tid & 3;
            float4 v = make_float4(0.f, 0.f, 0.f, 0.f);
            if (col0 + bn < CK)
                v = B4[(size_t)(col0 + bn)*192 + (k0 >> 2) + fc];
            Bs[(fc*4+0)*BSTR + bn] = v.x;
            Bs[(fc*4+1)*BSTR + bn] = v.y;
            Bs[(fc*4+2)*BSTR + bn] = v.z;
            Bs[(fc*4+3)*BSTR + bn] = v.w;
        }
        __syncthreads();

#pragma unroll
        for (int kk = 0; kk < BK; kk++) {
            float4 b0 = *(const float4*)&Bs[kk*BSTR + tx*4];
            F2 bp0; bp0.f = make_float2(b0.x, b0.y);
            F2 bp1; bp1.f = make_float2(b0.z, b0.w);
            float4 a0 = *(const float4*)&As[kk*ASTR + ty*8];
            float4 a1 = *(const float4*)&As[kk*ASTR + ty*8 + 4];
            float a[8] = {a0.x, a0.y, a0.z, a0.w, a1.x, a1.y, a1.z, a1.w};
#pragma unroll
            for (int i = 0; i < 8; i++) {
                F2 aa; aa.f = make_float2(a[i], a[i]);
                ffma2(acc[i][0], aa, bp0);
                ffma2(acc[i][1], aa, bp1);
            }
        }
        __syncthreads();
    }

#pragma unroll
    for (int i = 0; i < 8; i++) {
        int m = row0 + ty*8 + i;
        float vals[4] = {acc[i][0].f.x, acc[i][0].f.y, acc[i][1].f.x, acc[i][1].f.y};
#pragma unroll
        for (int j = 0; j < 4; j++) {
            int n = col0 + tx*4 + j;
            if (n < CK) Cout[(size_t)m*CK + n] = vals[j];
        }
    }
}

// ---------------- kernel 4: mean over patches ----------------
__global__ void mean_img(const float* __restrict__ L, float* __restrict__ img) {
    int ck = blockIdx.x * 256 + threadIdx.x;
    int b = blockIdx.y;
    if (ck >= CK) return;
    const float* base = L + (size_t)b * NP * CK + ck;
    float s = 0.0f;
    for (int n = 0; n < NP; n++) s += base[(size_t)n * CK];
    img[b*CK + ck] = s * (1.0f/256.0f);
}

// ---------------- kernel 5: class logits ----------------
__global__ void cls_logits(const float* __restrict__ img, const float* __restrict__ sa,
                           const float* __restrict__ scale_p, float* __restrict__ out) {
    int idx = blockIdx.x * 256 + threadIdx.x;
    if (idx >= SZ_CLS) return;
    int b = idx / (C_CLS-1), c = idx % (C_CLS-1);
    float s[K_PROT], mx = -1e30f;
#pragma unroll
    for (int k = 0; k < K_PROT; k++) { s[k] = sa[c*K_PROT + k]; mx = fmaxf(mx, s[k]); }
    float den = 0.0f;
#pragma unroll
    for (int k = 0; k < K_PROT; k++) { s[k] = expf(s[k] - mx); den += s[k]; }
    float scale = scale_p[0];
    float acc = 0.0f;
#pragma unroll
    for (int k = 0; k < K_PROT; k++)
        acc += scale * img[b*CK + c*K_PROT + k] * (s[k] / den * (float)K_PROT);
    out[idx] = acc;
}

// ---------------- kernel 6: pseudo labels + per-class row lists ----------------
__global__ void pseudo_k(const int* __restrict__ labels, const unsigned* __restrict__ masks,
                         float* __restrict__ out_pl) {
    int bn = blockIdx.x * 256 + threadIdx.x;     // < 16384
    int b = bn >> 8;
    int lab = labels[b];
    int pl = (masks[bn] != 0u) ? lab : (C_CLS - 1);
    g_pl[bn] = pl;
    out_pl[bn] = (float)pl;
    int pos = atomicAdd(&g_count[pl], 1);
    g_rowlist[pl*BN_TOT + pos] = bn;
}

// ---------------- kernel 7: per-class masked Sinkhorn + argmax ----------------
__global__ void __launch_bounds__(256) sinkhorn_k(const float* __restrict__ L,
                                                  float* __restrict__ out_part) {
    int c = blockIdx.x;
    int M = g_count[c];
    if (M == 0) return;                 // uniform per block
    int tid = threadIdx.x;
    int lane = tid & 31;
    __shared__ float s_col[K_PROT];
    const int* rl = g_rowlist + c*BN_TOT;

    float ps[K_PROT];
#pragma unroll
    for (int k = 0; k < K_PROT; k++) ps[k] = 0.0f;

    // init: Q = softmax(L[n, c, :]) over own rows; accumulate column partials
    for (int r = tid; r < M; r += 256) {
        int n = rl[r];
        const float* lp = L + (size_t)n*CK + c*K_PROT;
        float q[K_PROT], mx = lp[0];
#pragma unroll
        for (int k = 0; k < K_PROT; k++) { q[k] = lp[k]; mx = fmaxf(mx, q[k]); }
        float den = 0.0f;
#pragma unroll
        for (int k = 0; k < K_PROT; k++) { q[k] = expf(q[k] - mx); den += q[k]; }
#pragma unroll
        for (int k = 0; k < K_PROT; k++) {
            q[k] = q[k] / den;
            g_Q[n*K_PROT + k] = q[k];
            ps[k] += q[k];
        }
    }

    for (int it = 0; it < 3; it++) {
        __syncthreads();
        if (tid < K_PROT) s_col[tid] = 0.0f;
        __syncthreads();
#pragma unroll
        for (int k = 0; k < K_PROT; k++) {
            float v = ps[k];
#pragma unroll
            for (int o = 16; o; o >>= 1) v += __shfl_xor_sync(0xffffffffu, v, o);
            if (lane == 0) atomicAdd(&s_col[k], v);
        }
        __syncthreads();
        float sc[K_PROT];
#pragma unroll
        for (int k = 0; k < K_PROT; k++) sc[k] = s_col[k] + EPSV;

        float nps[K_PROT];
#pragma unroll
        for (int k = 0; k < K_PROT; k++) nps[k] = 0.0f;

        for (int r = tid; r < M; r += 256) {
            int n = rl[r];
            float q[K_PROT], rs = 0.0f;
#pragma unroll
            for (int k = 0; k < K_PROT; k++) {
                q[k] = g_Q[n*K_PROT + k] / sc[k];
                rs += q[k];
            }
            rs += EPSV;
            float best = -1.0f; int bi = 0;
#pragma unroll
            for (int k = 0; k < K_PROT; k++) {
                q[k] = q[k] / rs;
                g_Q[n*K_PROT + k] = q[k];
                nps[k] += q[k];
            }
            if (it == 2) {
                best = q[0]; bi = 0;
#pragma unroll
                for (int k = 1; k < K_PROT; k++)
                    if (q[k] > best) { best = q[k]; bi = k; }
                out_part[n] = (float)bi;
            }
        }
#pragma unroll
        for (int k = 0; k < K_PROT; k++) ps[k] = nps[k];
    }
}

// ---------------- kernel 8: prototype candidates  P_new[c] = Q_c^T @ tok ----------------
__global__ void __launch_bounds__(256) pnew_k() {
    int c = blockIdx.y;
    int M = g_count[c];
    int start = blockIdx.x * 256;
    if (start >= M) return;             // uniform per block
    int nr = min(256, M - start);
    int tid = threadIdx.x;
    __shared__ int   rn[256];
    __shared__ float qs[256*K_PROT];

    if (tid < nr) rn[tid] = g_rowlist[c*BN_TOT + start + tid];
    __syncthreads();
    for (int i = tid; i < nr*K_PROT; i += 256)
        qs[i] = g_Q[rn[i / K_PROT]*K_PROT + (i % K_PROT)];
    __syncthreads();

    float acc[3][K_PROT];
#pragma unroll
    for (int j = 0; j < 3; j++)
#pragma unroll
        for (int k = 0; k < K_PROT; k++) acc[j][k] = 0.0f;

    for (int r = 0; r < nr; r++) {
        int n = rn[r];
        const float* tp = g_An + (size_t)n*DIM;
        float t0 = tp[tid], t1 = tp[tid + 256], t2 = tp[tid + 512];
#pragma unroll
        for (int k = 0; k < K_PROT; k++) {
            float q = qs[r*K_PROT + k];
            acc[0][k] += q * t0;
            acc[1][k] += q * t1;
            acc[2][k] += q * t2;
        }
    }
    float* P = g_Pacc + (size_t)c * (K_PROT*DIM);
#pragma unroll
    for (int k = 0; k < K_PROT; k++)
#pragma unroll
        for (int j = 0; j < 3; j++)
            atomicAdd(&P[k*DIM + tid + j*256], acc[j][k]);
}

// ---------------- kernel 9: EMA prototype update ----------------
__global__ void combine_k(const float* __restrict__ proto, float* __restrict__ out_np) {
    int i = blockIdx.x * 256 + threadIdx.x;     // < 771,840
    if (i >= SZ_NP) return;
    int c = i / (K_PROT*DIM);
    float p = proto[i];
    out_np[i] = (g_count[c] > 0) ? 0.999f*p + 0.001f*g_Pacc[i] : p;
}

// ---------------- launch ----------------
extern "C" void kernel_launch(void* const* d_in, const int* in_sizes, int n_in,
                              void* d_out, int out_size) {
    const float*    tok    = (const float*)d_in[0];
    const float*    proto  = (const float*)d_in[1];
    const float*    sa     = (const float*)d_in[2];
    const float*    scale  = (const float*)d_in[3];
    const int*      labels = (const int*)d_in[4];
    const unsigned* masks  = (const unsigned*)d_in[5];  // 0/1 whether stored as i32 or f32

    float* out      = (float*)d_out;
    float* out_pp   = out;
    float* out_img  = out_pp  + SZ_PP;
    float* out_cls  = out_img + SZ_IMG;
    float* out_part = out_cls + SZ_CLS;
    float* out_np   = out_part + SZ_PART;
    float* out_pl   = out_np  + SZ_NP;

    zero_k<<<(SZ_NP + 255)/256, 256>>>();
    norm_rows<0><<<BN_TOT/8, 256>>>(tok, BN_TOT);
    norm_rows<1><<<(CK + 7)/8, 256>>>(proto, CK);
    {
        dim3 grid((CK + BN - 1)/BN, BN_TOT/BM);   // (16, 128)
        gemm_nt<<<grid, 256>>>(out_pp);
    }
    {
        dim3 grid((CK + 255)/256, B_IMG);
        mean_img<<<grid, 256>>>(out_pp, out_img);
    }
    cls_logits<<<(SZ_CLS + 255)/256, 256>>>(out_img, sa, scale, out_cls);
    pseudo_k<<<BN_TOT/256, 256>>>(labels, masks, out_pl);
    sinkhorn_k<<<C_CLS, 256>>>(out_pp, out_part);
    {
        dim3 grid(BN_TOT/256, C_CLS);             // (64, 201), most blocks early-exit
        pnew_k<<<grid, 256>>>();
    }
    combine_k<<<(SZ_NP + 255)/256, 256>>>(proto, out_np);
}

// round 2
// speedup vs baseline: 1.1561x; 1.1561x over previous
#include <cuda_runtime.h>
#include <cstdint>

// ---------------- problem constants ----------------
#define C_CLS   201
#define K_PROT  5
#define DIM     768
#define B_IMG   64
#define NP      256
#define BN_TOT  (B_IMG*NP)     // 16384
#define CK      (C_CLS*K_PROT) // 1005
#define EPSV    1e-12f

#define SZ_PP   (BN_TOT*CK)
#define SZ_IMG  (B_IMG*CK)
#define SZ_CLS  (B_IMG*(C_CLS-1))
#define SZ_PART (BN_TOT)
#define SZ_NP   (C_CLS*K_PROT*DIM)

// ---------------- device scratch ----------------
__device__ float g_invA[BN_TOT];            // 1/(||tok row||+eps)
__device__ float g_invB[CK];                // 1/(||proto row||+eps)
__device__ int   g_rowlist[C_CLS*BN_TOT];
__device__ int   g_count[C_CLS];
__device__ float g_Q[BN_TOT*K_PROT];
__device__ float g_Pacc[C_CLS*K_PROT*DIM];
__device__ float g_part[128*1024];          // per row-tile column sums

// ---------------- helpers ----------------
union F2 { float2 f; unsigned long long u; };
__device__ __forceinline__ void ffma2(F2& d, const F2& a, const F2& b) {
    asm("fma.rn.f32x2 %0, %1, %2, %0;" : "+l"(d.u) : "l"(a.u), "l"(b.u));
}

// ---------------- kernel 0: zero scratch ----------------
__global__ void zero_k() {
    int i = blockIdx.x * 256 + threadIdx.x;
    if (i < SZ_NP)  g_Pacc[i] = 0.0f;
    if (i < C_CLS)  g_count[i] = 0;
}

// ---------------- kernel 1: row inverse norms (warp per row) ----------------
template <int MODE>   // 0 -> tokens, 1 -> prototypes
__global__ void rownorm(const float* __restrict__ in, int nrows) {
    int warp = (blockIdx.x * blockDim.x + threadIdx.x) >> 5;
    int lane = threadIdx.x & 31;
    if (warp >= nrows) return;
    const float4* ip = (const float4*)(in + (size_t)warp * DIM);
    float s = 0.0f;
#pragma unroll
    for (int j = 0; j < 6; j++) {
        float4 v = ip[lane + j*32];
        s += v.x*v.x + v.y*v.y + v.z*v.z + v.w*v.w;
    }
#pragma unroll
    for (int o = 16; o; o >>= 1) s += __shfl_xor_sync(0xffffffffu, s, o);
    if (lane == 0) {
        float inv = 1.0f / (sqrtf(s) + EPSV);
        if (MODE == 0) g_invA[warp] = inv; else g_invB[warp] = inv;
    }
}

// ---------------- kernel 2: GEMM 128x128x8, f32x2, dbl-buffered ----------------
// L = (tok*invA) @ (proto*invB)^T ; also emits per-block column sums for mean.
__global__ void __launch_bounds__(256, 2) gemm_nt(float* __restrict__ Cout,
                                                  const float* __restrict__ tokp,
                                                  const float* __restrict__ prop) {
    __shared__ __align__(16) float sm[4400];
    const int BSOFF = 2112;   // Bs base; each buffer 8*132=1056 floats

    int tid = threadIdx.x;
    int tx = tid & 15;            // N
    int ty = tid >> 4;            // M
    int row0 = blockIdx.y * 128;
    int col0 = blockIdx.x * 128;

    int fr = tid >> 1;            // 0..127
    int fc = tid & 1;             // which float4 of the 8-wide k chunk
    int arow = row0 + fr;
    int bcol = col0 + fr;
    bool bok = bcol < CK;
    float ivA = g_invA[arow];
    float ivB = bok ? g_invB[bcol] : 0.0f;

    const float4* A4 = (const float4*)tokp;   // row stride 192 float4
    const float4* B4 = (const float4*)prop;

    F2 acc[8][4];
#pragma unroll
    for (int i = 0; i < 8; i++)
#pragma unroll
        for (int p = 0; p < 4; p++) acc[i][p].u = 0ull;

    // preload stage 0
    float4 va = A4[(size_t)arow*192 + fc];
    float4 vb = bok ? B4[(size_t)bcol*192 + fc] : make_float4(0.f,0.f,0.f,0.f);
    {
        float* As = sm;             // buf 0
        float* Bs = sm + BSOFF;
        As[(fc*4+0)*132 + fr] = va.x*ivA;  As[(fc*4+1)*132 + fr] = va.y*ivA;
        As[(fc*4+2)*132 + fr] = va.z*ivA;  As[(fc*4+3)*132 + fr] = va.w*ivA;
        Bs[(fc*4+0)*132 + fr] = vb.x*ivB;  Bs[(fc*4+1)*132 + fr] = vb.y*ivB;
        Bs[(fc*4+2)*132 + fr] = vb.z*ivB;  Bs[(fc*4+3)*132 + fr] = vb.w*ivB;
    }

    int buf = 0;
    for (int s = 0; s < 96; s++) {
        __syncthreads();
        if (s < 95) {
            int kq = (s+1)*2;   // float4 offset
            va = A4[(size_t)arow*192 + kq + fc];
            vb = bok ? B4[(size_t)bcol*192 + kq + fc] : make_float4(0.f,0.f,0.f,0.f);
        }
        const float* As = sm + buf*1056;
        const float* Bs = sm + BSOFF + buf*1056;
#pragma unroll
        for (int kk = 0; kk < 8; kk++) {
            float4 a0 = *(const float4*)&As[kk*132 + ty*8];
            float4 a1 = *(const float4*)&As[kk*132 + ty*8 + 4];
            float4 b0 = *(const float4*)&Bs[kk*132 + tx*8];
            float4 b1 = *(const float4*)&Bs[kk*132 + tx*8 + 4];
            F2 bp[4];
            bp[0].f = make_float2(b0.x, b0.y);
            bp[1].f = make_float2(b0.z, b0.w);
            bp[2].f = make_float2(b1.x, b1.y);
            bp[3].f = make_float2(b1.z, b1.w);
            float av[8] = {a0.x,a0.y,a0.z,a0.w,a1.x,a1.y,a1.z,a1.w};
#pragma unroll
            for (int i = 0; i < 8; i++) {
                F2 aa; aa.f = make_float2(av[i], av[i]);
#pragma unroll
                for (int p = 0; p < 4; p++) ffma2(acc[i][p], aa, bp[p]);
            }
        }
        if (s < 95) {
            buf ^= 1;
            float* Aw = sm + buf*1056;
            float* Bw = sm + BSOFF + buf*1056;
            Aw[(fc*4+0)*132 + fr] = va.x*ivA;  Aw[(fc*4+1)*132 + fr] = va.y*ivA;
            Aw[(fc*4+2)*132 + fr] = va.z*ivA;  Aw[(fc*4+3)*132 + fr] = va.w*ivA;
            Bw[(fc*4+0)*132 + fr] = vb.x*ivB;  Bw[(fc*4+1)*132 + fr] = vb.y*ivB;
            Bw[(fc*4+2)*132 + fr] = vb.z*ivB;  Bw[(fc*4+3)*132 + fr] = vb.w*ivB;
        }
    }

    // epilogue: store C + per-block column sums (for patch mean)
    float cs[8];
#pragma unroll
    for (int j = 0; j < 8; j++) cs[j] = 0.0f;
#pragma unroll
    for (int i = 0; i < 8; i++) {
        size_t m = row0 + ty*8 + i;
        float vals[8];
#pragma unroll
        for (int p = 0; p < 4; p++) { vals[2*p] = acc[i][p].f.x; vals[2*p+1] = acc[i][p].f.y; }
#pragma unroll
        for (int j = 0; j < 8; j++) {
            int n = col0 + tx*8 + j;
            cs[j] += vals[j];
            if (n < CK) Cout[m*CK + n] = vals[j];
        }
    }
    __syncthreads();
#pragma unroll
    for (int j = 0; j < 8; j++) sm[ty*136 + tx*8 + j] = cs[j];
    __syncthreads();
    if (tid < 128) {
        float s = 0.0f;
#pragma unroll
        for (int t = 0; t < 16; t++) s += sm[t*136 + tid];
        g_part[blockIdx.y*1024 + col0 + tid] = s;
    }
}

// ---------------- kernel 3: combine partial sums -> image logits ----------------
__global__ void mean2(float* __restrict__ img) {
    int idx = blockIdx.x * 256 + threadIdx.x;
    if (idx >= SZ_IMG) return;
    int b = idx / CK, ck = idx % CK;
    img[idx] = (g_part[(2*b)*1024 + ck] + g_part[(2*b+1)*1024 + ck]) * (1.0f/256.0f);
}

// ---------------- kernel 4: class logits ----------------
__global__ void cls_logits(const float* __restrict__ img, const float* __restrict__ sa,
                           const float* __restrict__ scale_p, float* __restrict__ out) {
    int idx = blockIdx.x * 256 + threadIdx.x;
    if (idx >= SZ_CLS) return;
    int b = idx / (C_CLS-1), c = idx % (C_CLS-1);
    float s[K_PROT], mx = -1e30f;
#pragma unroll
    for (int k = 0; k < K_PROT; k++) { s[k] = sa[c*K_PROT + k]; mx = fmaxf(mx, s[k]); }
    float den = 0.0f;
#pragma unroll
    for (int k = 0; k < K_PROT; k++) { s[k] = expf(s[k] - mx); den += s[k]; }
    float scale = scale_p[0];
    float acc = 0.0f;
#pragma unroll
    for (int k = 0; k < K_PROT; k++)
        acc += scale * img[b*CK + c*K_PROT + k] * (s[k] / den * (float)K_PROT);
    out[idx] = acc;
}

// ---------------- kernel 5: pseudo labels + per-class row lists ----------------
__global__ void pseudo_k(const int* __restrict__ labels, const unsigned* __restrict__ masks,
                         float* __restrict__ out_pl) {
    int bn = blockIdx.x * 256 + threadIdx.x;
    int b = bn >> 8;
    int lab = labels[b];
    int pl = (masks[bn] != 0u) ? lab : (C_CLS - 1);
    out_pl[bn] = (float)pl;
    int pos = atomicAdd(&g_count[pl], 1);
    g_rowlist[pl*BN_TOT + pos] = bn;
}

// ---------------- kernel 6: per-class masked Sinkhorn + argmax ----------------
__global__ void __launch_bounds__(512) sinkhorn_k(const float* __restrict__ L,
                                                  float* __restrict__ out_part) {
    int c = blockIdx.x;
    int M = g_count[c];
    if (M == 0) return;
    int tid = threadIdx.x;
    int lane = tid & 31;
    __shared__ float s_col[K_PROT];
    const int* rl = g_rowlist + c*BN_TOT;

    float ps[K_PROT];
#pragma unroll
    for (int k = 0; k < K_PROT; k++) ps[k] = 0.0f;

    for (int r = tid; r < M; r += 512) {
        int n = rl[r];
        const float* lp = L + (size_t)n*CK + c*K_PROT;
        float q[K_PROT], mx = lp[0];
#pragma unroll
        for (int k = 0; k < K_PROT; k++) { q[k] = lp[k]; mx = fmaxf(mx, q[k]); }
        float den = 0.0f;
#pragma unroll
        for (int k = 0; k < K_PROT; k++) { q[k] = expf(q[k] - mx); den += q[k]; }
#pragma unroll
        for (int k = 0; k < K_PROT; k++) {
            q[k] = q[k] / den;
            g_Q[n*K_PROT + k] = q[k];
            ps[k] += q[k];
        }
    }

    for (int it = 0; it < 3; it++) {
        __syncthreads();
        if (tid < K_PROT) s_col[tid] = 0.0f;
        __syncthreads();
#pragma unroll
        for (int k = 0; k < K_PROT; k++) {
            float v = ps[k];
#pragma unroll
            for (int o = 16; o; o >>= 1) v += __shfl_xor_sync(0xffffffffu, v, o);
            if (lane == 0) atomicAdd(&s_col[k], v);
        }
        __syncthreads();
        float sc[K_PROT];
#pragma unroll
        for (int k = 0; k < K_PROT; k++) sc[k] = s_col[k] + EPSV;

        float nps[K_PROT];
#pragma unroll
        for (int k = 0; k < K_PROT; k++) nps[k] = 0.0f;

        for (int r = tid; r < M; r += 512) {
            int n = rl[r];
            float q[K_PROT], rs = 0.0f;
#pragma unroll
            for (int k = 0; k < K_PROT; k++) {
                q[k] = g_Q[n*K_PROT + k] / sc[k];
                rs += q[k];
            }
            rs += EPSV;
#pragma unroll
            for (int k = 0; k < K_PROT; k++) {
                q[k] = q[k] / rs;
                g_Q[n*K_PROT + k] = q[k];
                nps[k] += q[k];
            }
            if (it == 2) {
                float best = q[0]; int bi = 0;
#pragma unroll
                for (int k = 1; k < K_PROT; k++)
                    if (q[k] > best) { best = q[k]; bi = k; }
                out_part[n] = (float)bi;
            }
        }
#pragma unroll
        for (int k = 0; k < K_PROT; k++) ps[k] = nps[k];
    }
}

// ---------------- kernel 7: prototype candidates (64 rows/block, prefetched) ----------------
#define PR 64
__global__ void __launch_bounds__(256) pnew_k(const float* __restrict__ tok) {
    int c = blockIdx.y;
    int M = g_count[c];
    int start = blockIdx.x * PR;
    if (start >= M) return;
    int nr = min(PR, M - start);
    int tid = threadIdx.x;
    __shared__ int   rn[PR];
    __shared__ float qs[PR*K_PROT];

    if (tid < nr) rn[tid] = g_rowlist[c*BN_TOT + start + tid];
    __syncthreads();
    for (int i = tid; i < nr*K_PROT; i += 256) {
        int n = rn[i / K_PROT];
        qs[i] = g_Q[n*K_PROT + (i % K_PROT)] * g_invA[n];
    }
    __syncthreads();

    float acc[3][K_PROT];
#pragma unroll
    for (int j = 0; j < 3; j++)
#pragma unroll
        for (int k = 0; k < K_PROT; k++) acc[j][k] = 0.0f;

    const float* tp = tok + (size_t)rn[0]*DIM;
    float a0 = tp[tid], a1 = tp[tid+256], a2 = tp[tid+512];
    for (int r = 0; r < nr; r++) {
        float b0 = 0.f, b1 = 0.f, b2 = 0.f;
        if (r + 1 < nr) {
            const float* tq = tok + (size_t)rn[r+1]*DIM;
            b0 = tq[tid]; b1 = tq[tid+256]; b2 = tq[tid+512];
        }
#pragma unroll
        for (int k = 0; k < K_PROT; k++) {
            float q = qs[r*K_PROT + k];
            acc[0][k] += q * a0;
            acc[1][k] += q * a1;
            acc[2][k] += q * a2;
        }
        a0 = b0; a1 = b1; a2 = b2;
    }
    float* P = g_Pacc + (size_t)c * (K_PROT*DIM);
#pragma unroll
    for (int k = 0; k < K_PROT; k++)
#pragma unroll
        for (int j = 0; j < 3; j++)
            atomicAdd(&P[k*DIM + tid + j*256], acc[j][k]);
}

// ---------------- kernel 8: EMA prototype update ----------------
__global__ void combine_k(const float* __restrict__ proto, float* __restrict__ out_np) {
    int i = blockIdx.x * 256 + threadIdx.x;
    if (i >= SZ_NP) return;
    int c = i / (K_PROT*DIM);
    float p = proto[i];
    out_np[i] = (g_count[c] > 0) ? 0.999f*p + 0.001f*g_Pacc[i] : p;
}

// ---------------- launch ----------------
extern "C" void kernel_launch(void* const* d_in, const int* in_sizes, int n_in,
                              void* d_out, int out_size) {
    const float*    tok    = (const float*)d_in[0];
    const float*    proto  = (const float*)d_in[1];
    const float*    sa     = (const float*)d_in[2];
    const float*    scale  = (const float*)d_in[3];
    const int*      labels = (const int*)d_in[4];
    const unsigned* masks  = (const unsigned*)d_in[5];

    float* out      = (float*)d_out;
    float* out_pp   = out;
    float* out_img  = out_pp  + SZ_PP;
    float* out_cls  = out_img + SZ_IMG;
    float* out_part = out_cls + SZ_CLS;
    float* out_np   = out_part + SZ_PART;
    float* out_pl   = out_np  + SZ_NP;

    zero_k<<<(SZ_NP + 255)/256, 256>>>();
    rownorm<0><<<BN_TOT/8, 256>>>(tok, BN_TOT);
    rownorm<1><<<(CK + 7)/8, 256>>>(proto, CK);
    {
        dim3 grid((CK + 127)/128, BN_TOT/128);   // (8, 128)
        gemm_nt<<<grid, 256>>>(out_pp, tok, proto);
    }
    mean2<<<(SZ_IMG + 255)/256, 256>>>(out_img);
    cls_logits<<<(SZ_CLS + 255)/256, 256>>>(out_img, sa, scale, out_cls);
    pseudo_k<<<BN_TOT/256, 256>>>(labels, masks, out_pl);
    sinkhorn_k<<<C_CLS, 512>>>(out_pp, out_part);
    {
        dim3 grid(BN_TOT/PR, C_CLS);
        pnew_k<<<grid, 256>>>(tok);
    }
    combine_k<<<(SZ_NP + 255)/256, 256>>>(proto, out_np);
}

// round 5
// speedup vs baseline: 1.6503x; 1.4275x over previous
#include <cuda_runtime.h>
#include <cuda_bf16.h>
#include <cstdint>

// ---------------- problem constants ----------------
#define C_CLS   201
#define K_PROT  5
#define DIM     768
#define B_IMG   64
#define NP      256
#define BN_TOT  16384
#define CK      1005
#define NPAD    1024
#define KSPLIT  2304          // 3 * 768 (Ah|Ah|Al vs Bh|Bl|Bh)
#define EPSV    1e-12f

#define SZ_PP   (BN_TOT*CK)
#define SZ_IMG  (B_IMG*CK)
#define SZ_CLS  (B_IMG*(C_CLS-1))
#define SZ_PART (BN_TOT)
#define SZ_NP   (C_CLS*K_PROT*DIM)

// ---------------- device scratch ----------------
__device__ __nv_bfloat16 g_Abf[(size_t)BN_TOT*KSPLIT];   // 75.5 MB
__device__ __nv_bfloat16 g_Bbf[(size_t)NPAD*KSPLIT];     // 4.7 MB
__device__ float g_invA[BN_TOT];
__device__ int   g_rowlist[C_CLS*BN_TOT];
__device__ int   g_count[C_CLS];
__device__ float g_Q[BN_TOT*K_PROT];
__device__ float g_Pacc[SZ_NP];

__device__ __forceinline__ uint32_t smem_u32(const void* p) {
    uint32_t a;
    asm("{ .reg .u64 t; cvta.to.shared.u64 t, %1; cvt.u32.u64 %0, t; }" : "=r"(a) : "l"(p));
    return a;
}

// ---------------- kernel 0: zero scratch ----------------
__global__ void zero_k() {
    int i = blockIdx.x * 256 + threadIdx.x;
    if (i < SZ_NP)  g_Pacc[i] = 0.0f;
    if (i < C_CLS)  g_count[i] = 0;
}

// ---------------- conv: normalize + bf16 hi/lo split ----------------
// A' cols: [hi | hi | lo]   B' cols: [hi | lo | hi]
template <int MODE>   // 0: tokens -> g_Abf (+g_invA); 1: protos -> g_Bbf
__global__ void __launch_bounds__(256) conv_k(const float* __restrict__ in, int nrows) {
    int row = blockIdx.x;
    int tid = threadIdx.x;
    __shared__ float red[8];
    __nv_bfloat16* dst = (MODE == 0 ? g_Abf : g_Bbf) + (size_t)row * KSPLIT;

    if (MODE == 1 && row >= nrows) {
        __nv_bfloat16 z = __float2bfloat16(0.0f);
        for (int i = tid; i < KSPLIT; i += 256) dst[i] = z;
        return;
    }
    const float* rp = in + (size_t)row * DIM;
    float v[3]; float s = 0.0f;
#pragma unroll
    for (int i = 0; i < 3; i++) { v[i] = rp[tid + i*256]; s += v[i]*v[i]; }
#pragma unroll
    for (int o = 16; o; o >>= 1) s += __shfl_xor_sync(0xffffffffu, s, o);
    if ((tid & 31) == 0) red[tid >> 5] = s;
    __syncthreads();
    float tot = 0.0f;
#pragma unroll
    for (int w = 0; w < 8; w++) tot += red[w];
    float inv = 1.0f / (sqrtf(tot) + EPSV);
    if (MODE == 0 && tid == 0) g_invA[row] = inv;
#pragma unroll
    for (int i = 0; i < 3; i++) {
        float a = v[i] * inv;
        __nv_bfloat16 hi = __float2bfloat16(a);
        __nv_bfloat16 lo = __float2bfloat16(a - __bfloat162float(hi));
        int c = tid + i*256;
        if (MODE == 0) {
            dst[c] = hi; dst[768 + c] = hi; dst[1536 + c] = lo;
        } else {
            dst[c] = hi; dst[768 + c] = lo; dst[1536 + c] = hi;
        }
    }
}

// ---------------- GEMM: mma.sync bf16, CTA 128x128, K=2304 ----------------
#define ASTR    40              // bf16 per smem row (80 B) -> conflict-free ldmatrix
#define NSTAGE  72              // 2304/32

__device__ __forceinline__ void ldsm4(uint32_t& r0, uint32_t& r1, uint32_t& r2, uint32_t& r3,
                                      uint32_t addr) {
    asm volatile("ldmatrix.sync.aligned.m8n8.x4.shared.b16 {%0,%1,%2,%3}, [%4];"
                 : "=r"(r0), "=r"(r1), "=r"(r2), "=r"(r3) : "r"(addr));
}
__device__ __forceinline__ void mma16816(float* c, const uint32_t* a, const uint32_t* b) {
    asm volatile("mma.sync.aligned.m16n8k16.row.col.f32.bf16.bf16.f32 "
                 "{%0,%1,%2,%3}, {%4,%5,%6,%7}, {%8,%9}, {%0,%1,%2,%3};"
                 : "+f"(c[0]), "+f"(c[1]), "+f"(c[2]), "+f"(c[3])
                 : "r"(a[0]), "r"(a[1]), "r"(a[2]), "r"(a[3]), "r"(b[0]), "r"(b[1]));
}

__global__ void __launch_bounds__(256, 2) gemm_mma(float* __restrict__ Cout) {
    __shared__ __align__(16) __nv_bfloat16 As[2][128*ASTR];
    __shared__ __align__(16) __nv_bfloat16 Bs[2][128*ASTR];

    int tid = threadIdx.x;
    int lane = tid & 31;
    int warp = tid >> 5;
    int wm = warp & 3;          // 0..3 -> m offset 32*wm
    int wn = warp >> 2;         // 0..1 -> n offset 64*wn
    int row0 = blockIdx.y * 128;
    int col0 = blockIdx.x * 128;

    // global load mapping: row = tid>>1, two float4 (= 16 bf16) per thread per tile
    int lr = tid >> 1;
    int lf = (tid & 1) * 2;
    const float4* A4 = (const float4*)g_Abf;   // 288 f4 per row
    const float4* B4 = (const float4*)g_Bbf;
    size_t a_goff = (size_t)(row0 + lr) * 288 + lf;
    size_t b_goff = (size_t)(col0 + lr) * 288 + lf;

    // ldmatrix lane offsets
    uint32_t a_lane = (uint32_t)((((lane >> 3) & 1)*8 + (lane & 7))*80 + ((lane >> 4) & 1)*16);
    uint32_t b_lane = (uint32_t)((((lane >> 4) & 1)*8 + (lane & 7))*80 + ((lane >> 3) & 1)*16);
    uint32_t a_base = smem_u32(&As[0][0]) + (uint32_t)(wm*32)*80 + a_lane;
    uint32_t b_base = smem_u32(&Bs[0][0]) + (uint32_t)(wn*64)*80 + b_lane;

    float acc[2][8][4];
#pragma unroll
    for (int i = 0; i < 2; i++)
#pragma unroll
        for (int j = 0; j < 8; j++)
#pragma unroll
            for (int r = 0; r < 4; r++) acc[i][j][r] = 0.0f;

    // preload stage 0
    float4 va0 = A4[a_goff], va1 = A4[a_goff + 1];
    float4 vb0 = B4[b_goff], vb1 = B4[b_goff + 1];
    *(float4*)(As[0] + lr*ASTR + lf*8)     = va0;
    *(float4*)(As[0] + lr*ASTR + lf*8 + 8) = va1;
    *(float4*)(Bs[0] + lr*ASTR + lf*8)     = vb0;
    *(float4*)(Bs[0] + lr*ASTR + lf*8 + 8) = vb1;
    __syncthreads();

    for (int s = 0; s < NSTAGE; s++) {
        int buf = s & 1;
        if (s + 1 < NSTAGE) {
            size_t off = (size_t)(s + 1) * 4;
            va0 = A4[a_goff + off]; va1 = A4[a_goff + off + 1];
            vb0 = B4[b_goff + off]; vb1 = B4[b_goff + off + 1];
        }
        uint32_t abuf = a_base + buf * (uint32_t)(128*80);
        uint32_t bbuf = b_base + buf * (uint32_t)(128*80);
#pragma unroll
        for (int ks = 0; ks < 2; ks++) {
            uint32_t af[2][4];
            ldsm4(af[0][0], af[0][1], af[0][2], af[0][3], abuf + ks*32);
            ldsm4(af[1][0], af[1][1], af[1][2], af[1][3], abuf + ks*32 + 16*80);
            uint32_t bf[4][4];
#pragma unroll
            for (int j = 0; j < 4; j++)
                ldsm4(bf[j][0], bf[j][1], bf[j][2], bf[j][3], bbuf + ks*32 + j*16*80);
#pragma unroll
            for (int im = 0; im < 2; im++)
#pragma unroll
                for (int j = 0; j < 4; j++) {
                    mma16816(acc[im][2*j],   af[im], &bf[j][0]);
                    mma16816(acc[im][2*j+1], af[im], &bf[j][2]);
                }
        }
        if (s + 1 < NSTAGE) {
            int nb = (s + 1) & 1;
            *(float4*)(As[nb] + lr*ASTR + lf*8)     = va0;
            *(float4*)(As[nb] + lr*ASTR + lf*8 + 8) = va1;
            *(float4*)(Bs[nb] + lr*ASTR + lf*8)     = vb0;
            *(float4*)(Bs[nb] + lr*ASTR + lf*8 + 8) = vb1;
        }
        __syncthreads();
    }

    // epilogue: scalar stores (CK=1005 is odd -> rows not 8B aligned)
    int mb = row0 + wm*32 + (lane >> 2);
    int nb0 = col0 + wn*64 + (lane & 3)*2;
#pragma unroll
    for (int im = 0; im < 2; im++) {
        size_t r0 = (size_t)(mb + im*16) * CK;
        size_t r1 = (size_t)(mb + im*16 + 8) * CK;
#pragma unroll
        for (int j = 0; j < 8; j++) {
            int n = nb0 + j*8;
            if (n < CK) {
                Cout[r0 + n] = acc[im][j][0];
                Cout[r1 + n] = acc[im][j][2];
            }
            if (n + 1 < CK) {
                Cout[r0 + n + 1] = acc[im][j][1];
                Cout[r1 + n + 1] = acc[im][j][3];
            }
        }
    }
}

// ---------------- mean over patches ----------------
__global__ void mean_img(const float* __restrict__ L, float* __restrict__ img) {
    int ck = blockIdx.x * 256 + threadIdx.x;
    int b = blockIdx.y;
    if (ck >= CK) return;
    const float* base = L + (size_t)b * NP * CK + ck;
    float s = 0.0f;
    for (int n = 0; n < NP; n++) s += base[(size_t)n * CK];
    img[b*CK + ck] = s * (1.0f/256.0f);
}

// ---------------- class logits ----------------
__global__ void cls_logits(const float* __restrict__ img, const float* __restrict__ sa,
                           const float* __restrict__ scale_p, float* __restrict__ out) {
    int idx = blockIdx.x * 256 + threadIdx.x;
    if (idx >= SZ_CLS) return;
    int b = idx / (C_CLS-1), c = idx % (C_CLS-1);
    float s[K_PROT], mx = -1e30f;
#pragma unroll
    for (int k = 0; k < K_PROT; k++) { s[k] = sa[c*K_PROT + k]; mx = fmaxf(mx, s[k]); }
    float den = 0.0f;
#pragma unroll
    for (int k = 0; k < K_PROT; k++) { s[k] = expf(s[k] - mx); den += s[k]; }
    float scale = scale_p[0];
    float acc = 0.0f;
#pragma unroll
    for (int k = 0; k < K_PROT; k++)
        acc += scale * img[b*CK + c*K_PROT + k] * (s[k] / den * (float)K_PROT);
    out[idx] = acc;
}

// ---------------- pseudo labels + per-class row lists ----------------
__global__ void pseudo_k(const int* __restrict__ labels, const unsigned* __restrict__ masks,
                         float* __restrict__ out_pl) {
    int bn = blockIdx.x * 256 + threadIdx.x;
    int b = bn >> 8;
    int lab = labels[b];
    int pl = (masks[bn] != 0u) ? lab : (C_CLS - 1);
    out_pl[bn] = (float)pl;
    int pos = atomicAdd(&g_count[pl], 1);
    g_rowlist[pl*BN_TOT + pos] = bn;
}

// ---------------- per-class masked Sinkhorn + argmax ----------------
__global__ void __launch_bounds__(512) sinkhorn_k(const float* __restrict__ L,
                                                  float* __restrict__ out_part) {
    int c = blockIdx.x;
    int M = g_count[c];
    if (M == 0) return;
    int tid = threadIdx.x;
    int lane = tid & 31;
    __shared__ float s_col[K_PROT];
    const int* rl = g_rowlist + c*BN_TOT;

    float ps[K_PROT];
#pragma unroll
    for (int k = 0; k < K_PROT; k++) ps[k] = 0.0f;

    for (int r = tid; r < M; r += 512) {
        int n = rl[r];
        const float* lp = L + (size_t)n*CK + c*K_PROT;
        float q[K_PROT], mx = lp[0];
#pragma unroll
        for (int k = 0; k < K_PROT; k++) { q[k] = lp[k]; mx = fmaxf(mx, q[k]); }
        float den = 0.0f;
#pragma unroll
        for (int k = 0; k < K_PROT; k++) { q[k] = expf(q[k] - mx); den += q[k]; }
#pragma unroll
        for (int k = 0; k < K_PROT; k++) {
            q[k] = q[k] / den;
            g_Q[n*K_PROT + k] = q[k];
            ps[k] += q[k];
        }
    }

    for (int it = 0; it < 3; it++) {
        __syncthreads();
        if (tid < K_PROT) s_col[tid] = 0.0f;
        __syncthreads();
#pragma unroll
        for (int k = 0; k < K_PROT; k++) {
            float v = ps[k];
#pragma unroll
            for (int o = 16; o; o >>= 1) v += __shfl_xor_sync(0xffffffffu, v, o);
            if (lane == 0) atomicAdd(&s_col[k], v);
        }
        __syncthreads();
        float sc[K_PROT];
#pragma unroll
        for (int k = 0; k < K_PROT; k++) sc[k] = s_col[k] + EPSV;

        float nps[K_PROT];
#pragma unroll
        for (int k = 0; k < K_PROT; k++) nps[k] = 0.0f;

        for (int r = tid; r < M; r += 512) {
            int n = rl[r];
            float q[K_PROT], rs = 0.0f;
#pragma unroll
            for (int k = 0; k < K_PROT; k++) {
                q[k] = g_Q[n*K_PROT + k] / sc[k];
                rs += q[k];
            }
            rs += EPSV;
#pragma unroll
            for (int k = 0; k < K_PROT; k++) {
                q[k] = q[k] / rs;
                g_Q[n*K_PROT + k] = q[k];
                nps[k] += q[k];
            }
            if (it == 2) {
                float best = q[0]; int bi = 0;
#pragma unroll
                for (int k = 1; k < K_PROT; k++)
                    if (q[k] > best) { best = q[k]; bi = k; }
                out_part[n] = (float)bi;
            }
        }
#pragma unroll
        for (int k = 0; k < K_PROT; k++) ps[k] = nps[k];
    }
}

// ---------------- prototype candidates ----------------
#define PR 64
__global__ void __launch_bounds__(256) pnew_k(const float* __restrict__ tok) {
    int c = blockIdx.y;
    int M = g_count[c];
    int start = blockIdx.x * PR;
    if (start >= M) return;
    int nr = min(PR, M - start);
    int tid = threadIdx.x;
    __shared__ int   rn[PR];
    __shared__ float qs[PR*K_PROT];

    if (tid < nr) rn[tid] = g_rowlist[c*BN_TOT + start + tid];
    __syncthreads();
    for (int i = tid; i < nr*K_PROT; i += 256) {
        int n = rn[i / K_PROT];
        qs[i] = g_Q[n*K_PROT + (i % K_PROT)] * g_invA[n];
    }
    __syncthreads();

    float acc[3][K_PROT];
#pragma unroll
    for (int j = 0; j < 3; j++)
#pragma unroll
        for (int k = 0; k < K_PROT; k++) acc[j][k] = 0.0f;

    const float* tp = tok + (size_t)rn[0]*DIM;
    float a0 = tp[tid], a1 = tp[tid+256], a2 = tp[tid+512];
    for (int r = 0; r < nr; r++) {
        float b0 = 0.f, b1 = 0.f, b2 = 0.f;
        if (r + 1 < nr) {
            const float* tq = tok + (size_t)rn[r+1]*DIM;
            b0 = tq[tid]; b1 = tq[tid+256]; b2 = tq[tid+512];
        }
#pragma unroll
        for (int k = 0; k < K_PROT; k++) {
            float q = qs[r*K_PROT + k];
            acc[0][k] += q * a0;
            acc[1][k] += q * a1;
            acc[2][k] += q * a2;
        }
        a0 = b0; a1 = b1; a2 = b2;
    }
    float* P = g_Pacc + (size_t)c * (K_PROT*DIM);
#pragma unroll
    for (int k = 0; k < K_PROT; k++)
#pragma unroll
        for (int j = 0; j < 3; j++)
            atomicAdd(&P[k*DIM + tid + j*256], acc[j][k]);
}

// ---------------- EMA prototype update ----------------
__global__ void combine_k(const float* __restrict__ proto, float* __restrict__ out_np) {
    int i = blockIdx.x * 256 + threadIdx.x;
    if (i >= SZ_NP) return;
    int c = i / (K_PROT*DIM);
    float p = proto[i];
    out_np[i] = (g_count[c] > 0) ? 0.999f*p + 0.001f*g_Pacc[i] : p;
}

// ---------------- launch ----------------
extern "C" void kernel_launch(void* const* d_in, const int* in_sizes, int n_in,
                              void* d_out, int out_size) {
    const float*    tok    = (const float*)d_in[0];
    const float*    proto  = (const float*)d_in[1];
    const float*    sa     = (const float*)d_in[2];
    const float*    scale  = (const float*)d_in[3];
    const int*      labels = (const int*)d_in[4];
    const unsigned* masks  = (const unsigned*)d_in[5];

    float* out      = (float*)d_out;
    float* out_pp   = out;
    float* out_img  = out_pp  + SZ_PP;
    float* out_cls  = out_img + SZ_IMG;
    float* out_part = out_cls + SZ_CLS;
    float* out_np   = out_part + SZ_PART;
    float* out_pl   = out_np  + SZ_NP;

    zero_k<<<(SZ_NP + 255)/256, 256>>>();
    conv_k<0><<<BN_TOT, 256>>>(tok, BN_TOT);
    conv_k<1><<<NPAD, 256>>>(proto, CK);
    {
        dim3 grid(NPAD/128, BN_TOT/128);   // (8, 128)
        gemm_mma<<<grid, 256>>>(out_pp);
    }
    {
        dim3 grid((CK + 255)/256, B_IMG);
        mean_img<<<grid, 256>>>(out_pp, out_img);
    }
    cls_logits<<<(SZ_CLS + 255)/256, 256>>>(out_img, sa, scale, out_cls);
    pseudo_k<<<BN_TOT/256, 256>>>(labels, masks, out_pl);
    sinkhorn_k<<<C_CLS, 512>>>(out_pp, out_part);
    {
        dim3 grid(BN_TOT/PR, C_CLS);
        pnew_k<<<grid, 256>>>(tok);
    }
    combine_k<<<(SZ_NP + 255)/256, 256>>>(proto, out_np);
}

// round 6
// speedup vs baseline: 1.6837x; 1.0203x over previous
#include <cuda_runtime.h>
#include <cuda_bf16.h>
#include <cstdint>

// ---------------- problem constants ----------------
#define C_CLS   201
#define K_PROT  5
#define DIM     768
#define B_IMG   64
#define NP      256
#define BN_TOT  16384
#define CK      1005
#define NPAD    1024
#define KSPLIT  2304          // 3 * 768 (Ah|Ah|Al vs Bh|Bl|Bh)
#define EPSV    1e-12f

#define SZ_PP   (BN_TOT*CK)
#define SZ_IMG  (B_IMG*CK)
#define SZ_CLS  (B_IMG*(C_CLS-1))
#define SZ_PART (BN_TOT)
#define SZ_NP   (C_CLS*K_PROT*DIM)

// ---------------- device scratch ----------------
__device__ __nv_bfloat16 g_Abf[(size_t)BN_TOT*KSPLIT];   // 75.5 MB
__device__ __nv_bfloat16 g_Bbf[(size_t)NPAD*KSPLIT];     // 4.7 MB
__device__ float g_invA[BN_TOT];
__device__ int   g_rowlist[C_CLS*BN_TOT];
__device__ int   g_count[C_CLS];
__device__ float g_Q[BN_TOT*K_PROT];
__device__ float g_Pacc[SZ_NP];

__device__ __forceinline__ uint32_t smem_u32(const void* p) {
    uint32_t a;
    asm("{ .reg .u64 t; cvta.to.shared.u64 t, %1; cvt.u32.u64 %0, t; }" : "=r"(a) : "l"(p));
    return a;
}

// ---------------- kernel 0: zero scratch ----------------
__global__ void zero_k() {
    int i = blockIdx.x * 256 + threadIdx.x;
    if (i < SZ_NP)  g_Pacc[i] = 0.0f;
    if (i < C_CLS)  g_count[i] = 0;
}

// ---------------- conv: normalize + bf16 hi/lo split ----------------
// A' cols: [hi | hi | lo]   B' cols: [hi | lo | hi]
template <int MODE>   // 0: tokens -> g_Abf (+g_invA); 1: protos -> g_Bbf
__global__ void __launch_bounds__(256) conv_k(const float* __restrict__ in, int nrows) {
    int row = blockIdx.x;
    int tid = threadIdx.x;
    __shared__ float red[8];
    __nv_bfloat16* dst = (MODE == 0 ? g_Abf : g_Bbf) + (size_t)row * KSPLIT;

    if (MODE == 1 && row >= nrows) {
        __nv_bfloat16 z = __float2bfloat16(0.0f);
        for (int i = tid; i < KSPLIT; i += 256) dst[i] = z;
        return;
    }
    const float* rp = in + (size_t)row * DIM;
    float v[3]; float s = 0.0f;
#pragma unroll
    for (int i = 0; i < 3; i++) { v[i] = rp[tid + i*256]; s += v[i]*v[i]; }
#pragma unroll
    for (int o = 16; o; o >>= 1) s += __shfl_xor_sync(0xffffffffu, s, o);
    if ((tid & 31) == 0) red[tid >> 5] = s;
    __syncthreads();
    float tot = 0.0f;
#pragma unroll
    for (int w = 0; w < 8; w++) tot += red[w];
    float inv = 1.0f / (sqrtf(tot) + EPSV);
    if (MODE == 0 && tid == 0) g_invA[row] = inv;
#pragma unroll
    for (int i = 0; i < 3; i++) {
        float a = v[i] * inv;
        __nv_bfloat16 hi = __float2bfloat16(a);
        __nv_bfloat16 lo = __float2bfloat16(a - __bfloat162float(hi));
        int c = tid + i*256;
        if (MODE == 0) {
            dst[c] = hi; dst[768 + c] = hi; dst[1536 + c] = lo;
        } else {
            dst[c] = hi; dst[768 + c] = lo; dst[1536 + c] = hi;
        }
    }
}

// ---------------- GEMM: mma.sync bf16, CTA 128x128, 4 warps 64x64, cp.async x4 ----------------
#define NSTAGE  72              // 2304/32
#define STAGES  4
#define STG_BYTES 20480         // (128*40 A + 128*40 B) bf16 = 2*10240 B

__device__ __forceinline__ void ldsm4(uint32_t& r0, uint32_t& r1, uint32_t& r2, uint32_t& r3,
                                      uint32_t addr) {
    asm volatile("ldmatrix.sync.aligned.m8n8.x4.shared.b16 {%0,%1,%2,%3}, [%4];"
                 : "=r"(r0), "=r"(r1), "=r"(r2), "=r"(r3) : "r"(addr));
}
__device__ __forceinline__ void mma16816(float* c, const uint32_t* a, const uint32_t* b) {
    asm volatile("mma.sync.aligned.m16n8k16.row.col.f32.bf16.bf16.f32 "
                 "{%0,%1,%2,%3}, {%4,%5,%6,%7}, {%8,%9}, {%0,%1,%2,%3};"
                 : "+f"(c[0]), "+f"(c[1]), "+f"(c[2]), "+f"(c[3])
                 : "r"(a[0]), "r"(a[1]), "r"(a[2]), "r"(a[3]), "r"(b[0]), "r"(b[1]));
}
__device__ __forceinline__ void cpa16(uint32_t dst, const void* src) {
    asm volatile("cp.async.cg.shared.global [%0], [%1], 16;" :: "r"(dst), "l"(src));
}

__global__ void __launch_bounds__(128, 2) gemm_mma(float* __restrict__ Cout) {
    extern __shared__ char sm[];

    int tid = threadIdx.x;
    int lane = tid & 31;
    int warp = tid >> 5;
    int wm = warp & 1;            // m offset 64*wm
    int wn = warp >> 1;           // n offset 64*wn
    int row0 = blockIdx.y * 128;
    int col0 = blockIdx.x * 128;

    uint32_t sbase = smem_u32(sm);
    const char* gA = (const char*)g_Abf + (size_t)(row0 + tid) * (KSPLIT*2);
    const char* gB = (const char*)g_Bbf + (size_t)(col0 + tid) * (KSPLIT*2);

    uint32_t a_lane = (uint32_t)((((lane >> 3) & 1)*8 + (lane & 7))*80 + ((lane >> 4) & 1)*16);
    uint32_t b_lane = (uint32_t)((((lane >> 4) & 1)*8 + (lane & 7))*80 + ((lane >> 3) & 1)*16);
    uint32_t a_off = (uint32_t)(wm*64)*80 + a_lane;
    uint32_t b_off = 10240u + (uint32_t)(wn*64)*80 + b_lane;

    float acc[4][8][4];
#pragma unroll
    for (int i = 0; i < 4; i++)
#pragma unroll
        for (int j = 0; j < 8; j++)
#pragma unroll
            for (int r = 0; r < 4; r++) acc[i][j][r] = 0.0f;

    // prologue: issue stages 0..2
#pragma unroll
    for (int p = 0; p < STAGES - 1; p++) {
        uint32_t dA = sbase + p*STG_BYTES + tid*80;
        const char* pA = gA + p*64;
        const char* pB = gB + p*64;
#pragma unroll
        for (int c = 0; c < 4; c++) {
            cpa16(dA + c*16, pA + c*16);
            cpa16(dA + 10240 + c*16, pB + c*16);
        }
        asm volatile("cp.async.commit_group;" ::: "memory");
    }

    for (int s = 0; s < NSTAGE; s++) {
        asm volatile("cp.async.wait_group 2;" ::: "memory");
        __syncthreads();
        uint32_t stg = sbase + (uint32_t)(s & 3)*STG_BYTES;
        uint32_t ab = stg + a_off;
        uint32_t bb = stg + b_off;
#pragma unroll
        for (int ks = 0; ks < 2; ks++) {
            uint32_t af[4][4], bf[4][4];
#pragma unroll
            for (int i = 0; i < 4; i++)
                ldsm4(af[i][0], af[i][1], af[i][2], af[i][3], ab + ks*32 + i*16*80);
#pragma unroll
            for (int j = 0; j < 4; j++)
                ldsm4(bf[j][0], bf[j][1], bf[j][2], bf[j][3], bb + ks*32 + j*16*80);
#pragma unroll
            for (int im = 0; im < 4; im++)
#pragma unroll
                for (int j = 0; j < 4; j++) {
                    mma16816(acc[im][2*j],   af[im], &bf[j][0]);
                    mma16816(acc[im][2*j+1], af[im], &bf[j][2]);
                }
        }
        if (s + STAGES - 1 < NSTAGE) {
            int p = s + STAGES - 1;
            uint32_t dA = sbase + (uint32_t)(p & 3)*STG_BYTES + tid*80;
            const char* pA = gA + p*64;
            const char* pB = gB + p*64;
#pragma unroll
            for (int c = 0; c < 4; c++) {
                cpa16(dA + c*16, pA + c*16);
                cpa16(dA + 10240 + c*16, pB + c*16);
            }
        }
        asm volatile("cp.async.commit_group;" ::: "memory");
    }

    // epilogue: scalar stores (CK=1005 odd -> rows not 8B aligned)
    int mb = row0 + wm*64 + (lane >> 2);
    int nb0 = col0 + wn*64 + (lane & 3)*2;
#pragma unroll
    for (int im = 0; im < 4; im++) {
        size_t r0 = (size_t)(mb + im*16) * CK;
        size_t r1 = (size_t)(mb + im*16 + 8) * CK;
#pragma unroll
        for (int j = 0; j < 8; j++) {
            int n = nb0 + j*8;
            if (n < CK) {
                Cout[r0 + n] = acc[im][j][0];
                Cout[r1 + n] = acc[im][j][2];
            }
            if (n + 1 < CK) {
                Cout[r0 + n + 1] = acc[im][j][1];
                Cout[r1 + n + 1] = acc[im][j][3];
            }
        }
    }
}

// ---------------- mean over patches ----------------
__global__ void mean_img(const float* __restrict__ L, float* __restrict__ img) {
    int ck = blockIdx.x * 256 + threadIdx.x;
    int b = blockIdx.y;
    if (ck >= CK) return;
    const float* base = L + (size_t)b * NP * CK + ck;
    float s = 0.0f;
    for (int n = 0; n < NP; n++) s += base[(size_t)n * CK];
    img[b*CK + ck] = s * (1.0f/256.0f);
}

// ---------------- class logits ----------------
__global__ void cls_logits(const float* __restrict__ img, const float* __restrict__ sa,
                           const float* __restrict__ scale_p, float* __restrict__ out) {
    int idx = blockIdx.x * 256 + threadIdx.x;
    if (idx >= SZ_CLS) return;
    int b = idx / (C_CLS-1), c = idx % (C_CLS-1);
    float s[K_PROT], mx = -1e30f;
#pragma unroll
    for (int k = 0; k < K_PROT; k++) { s[k] = sa[c*K_PROT + k]; mx = fmaxf(mx, s[k]); }
    float den = 0.0f;
#pragma unroll
    for (int k = 0; k < K_PROT; k++) { s[k] = expf(s[k] - mx); den += s[k]; }
    float scale = scale_p[0];
    float acc = 0.0f;
#pragma unroll
    for (int k = 0; k < K_PROT; k++)
        acc += scale * img[b*CK + c*K_PROT + k] * (s[k] / den * (float)K_PROT);
    out[idx] = acc;
}

// ---------------- pseudo labels + per-class row lists ----------------
__global__ void pseudo_k(const int* __restrict__ labels, const unsigned* __restrict__ masks,
                         float* __restrict__ out_pl) {
    int bn = blockIdx.x * 256 + threadIdx.x;
    int b = bn >> 8;
    int lab = labels[b];
    int pl = (masks[bn] != 0u) ? lab : (C_CLS - 1);
    out_pl[bn] = (float)pl;
    int pos = atomicAdd(&g_count[pl], 1);
    g_rowlist[pl*BN_TOT + pos] = bn;
}

// ---------------- per-class masked Sinkhorn + argmax ----------------
__global__ void __launch_bounds__(512) sinkhorn_k(const float* __restrict__ L,
                                                  float* __restrict__ out_part) {
    int c = blockIdx.x;
    int M = g_count[c];
    if (M == 0) return;
    int tid = threadIdx.x;
    int lane = tid & 31;
    __shared__ float s_col[K_PROT];
    const int* rl = g_rowlist + c*BN_TOT;

    float ps[K_PROT];
#pragma unroll
    for (int k = 0; k < K_PROT; k++) ps[k] = 0.0f;

    for (int r = tid; r < M; r += 512) {
        int n = rl[r];
        const float* lp = L + (size_t)n*CK + c*K_PROT;
        float q[K_PROT], mx = lp[0];
#pragma unroll
        for (int k = 0; k < K_PROT; k++) { q[k] = lp[k]; mx = fmaxf(mx, q[k]); }
        float den = 0.0f;
#pragma unroll
        for (int k = 0; k < K_PROT; k++) { q[k] = expf(q[k] - mx); den += q[k]; }
#pragma unroll
        for (int k = 0; k < K_PROT; k++) {
            q[k] = q[k] / den;
            g_Q[n*K_PROT + k] = q[k];
            ps[k] += q[k];
        }
    }

    for (int it = 0; it < 3; it++) {
        __syncthreads();
        if (tid < K_PROT) s_col[tid] = 0.0f;
        __syncthreads();
#pragma unroll
        for (int k = 0; k < K_PROT; k++) {
            float v = ps[k];
#pragma unroll
            for (int o = 16; o; o >>= 1) v += __shfl_xor_sync(0xffffffffu, v, o);
            if (lane == 0) atomicAdd(&s_col[k], v);
        }
        __syncthreads();
        float sc[K_PROT];
#pragma unroll
        for (int k = 0; k < K_PROT; k++) sc[k] = s_col[k] + EPSV;

        float nps[K_PROT];
#pragma unroll
        for (int k = 0; k < K_PROT; k++) nps[k] = 0.0f;

        for (int r = tid; r < M; r += 512) {
            int n = rl[r];
            float q[K_PROT], rs = 0.0f;
#pragma unroll
            for (int k = 0; k < K_PROT; k++) {
                q[k] = g_Q[n*K_PROT + k] / sc[k];
                rs += q[k];
            }
            rs += EPSV;
#pragma unroll
            for (int k = 0; k < K_PROT; k++) {
                q[k] = q[k] / rs;
                g_Q[n*K_PROT + k] = q[k];
                nps[k] += q[k];
            }
            if (it == 2) {
                float best = q[0]; int bi = 0;
#pragma unroll
                for (int k = 1; k < K_PROT; k++)
                    if (q[k] > best) { best = q[k]; bi = k; }
                out_part[n] = (float)bi;
            }
        }
#pragma unroll
        for (int k = 0; k < K_PROT; k++) ps[k] = nps[k];
    }
}

// ---------------- prototype candidates ----------------
#define PR 64
__global__ void __launch_bounds__(256) pnew_k(const float* __restrict__ tok) {
    int c = blockIdx.y;
    int M = g_count[c];
    int start = blockIdx.x * PR;
    if (start >= M) return;
    int nr = min(PR, M - start);
    int tid = threadIdx.x;
    __shared__ int   rn[PR];
    __shared__ float qs[PR*K_PROT];

    if (tid < nr) rn[tid] = g_rowlist[c*BN_TOT + start + tid];
    __syncthreads();
    for (int i = tid; i < nr*K_PROT; i += 256) {
        int n = rn[i / K_PROT];
        qs[i] = g_Q[n*K_PROT + (i % K_PROT)] * g_invA[n];
    }
    __syncthreads();

    float acc[3][K_PROT];
#pragma unroll
    for (int j = 0; j < 3; j++)
#pragma unroll
        for (int k = 0; k < K_PROT; k++) acc[j][k] = 0.0f;

    const float* tp = tok + (size_t)rn[0]*DIM;
    float a0 = tp[tid], a1 = tp[tid+256], a2 = tp[tid+512];
    for (int r = 0; r < nr; r++) {
        float b0 = 0.f, b1 = 0.f, b2 = 0.f;
        if (r + 1 < nr) {
            const float* tq = tok + (size_t)rn[r+1]*DIM;
            b0 = tq[tid]; b1 = tq[tid+256]; b2 = tq[tid+512];
        }
#pragma unroll
        for (int k = 0; k < K_PROT; k++) {
            float q = qs[r*K_PROT + k];
            acc[0][k] += q * a0;
            acc[1][k] += q * a1;
            acc[2][k] += q * a2;
        }
        a0 = b0; a1 = b1; a2 = b2;
    }
    float* P = g_Pacc + (size_t)c * (K_PROT*DIM);
#pragma unroll
    for (int k = 0; k < K_PROT; k++)
#pragma unroll
        for (int j = 0; j < 3; j++)
            atomicAdd(&P[k*DIM + tid + j*256], acc[j][k]);
}

// ---------------- EMA prototype update ----------------
__global__ void combine_k(const float* __restrict__ proto, float* __restrict__ out_np) {
    int i = blockIdx.x * 256 + threadIdx.x;
    if (i >= SZ_NP) return;
    int c = i / (K_PROT*DIM);
    float p = proto[i];
    out_np[i] = (g_count[c] > 0) ? 0.999f*p + 0.001f*g_Pacc[i] : p;
}

// ---------------- launch ----------------
extern "C" void kernel_launch(void* const* d_in, const int* in_sizes, int n_in,
                              void* d_out, int out_size) {
    const float*    tok    = (const float*)d_in[0];
    const float*    proto  = (const float*)d_in[1];
    const float*    sa     = (const float*)d_in[2];
    const float*    scale  = (const float*)d_in[3];
    const int*      labels = (const int*)d_in[4];
    const unsigned* masks  = (const unsigned*)d_in[5];

    float* out      = (float*)d_out;
    float* out_pp   = out;
    float* out_img  = out_pp  + SZ_PP;
    float* out_cls  = out_img + SZ_IMG;
    float* out_part = out_cls + SZ_CLS;
    float* out_np   = out_part + SZ_PART;
    float* out_pl   = out_np  + SZ_NP;

    const int GEMM_SMEM = STAGES * STG_BYTES;   // 81920
    cudaFuncSetAttribute(gemm_mma, cudaFuncAttributeMaxDynamicSharedMemorySize, GEMM_SMEM);

    zero_k<<<(SZ_NP + 255)/256, 256>>>();
    conv_k<0><<<BN_TOT, 256>>>(tok, BN_TOT);
    conv_k<1><<<NPAD, 256>>>(proto, CK);
    {
        dim3 grid(NPAD/128, BN_TOT/128);   // (8, 128)
        gemm_mma<<<grid, 128, GEMM_SMEM>>>(out_pp);
    }
    {
        dim3 grid((CK + 255)/256, B_IMG);
        mean_img<<<grid, 256>>>(out_pp, out_img);
    }
    cls_logits<<<(SZ_CLS + 255)/256, 256>>>(out_img, sa, scale, out_cls);
    pseudo_k<<<BN_TOT/256, 256>>>(labels, masks, out_pl);
    sinkhorn_k<<<C_CLS, 512>>>(out_pp, out_part);
    {
        dim3 grid(BN_TOT/PR, C_CLS);
        pnew_k<<<grid, 256>>>(tok);
    }
    combine_k<<<(SZ_NP + 255)/256, 256>>>(proto, out_np);
}

// round 7
// speedup vs baseline: 1.7871x; 1.0614x over previous
#include <cuda_runtime.h>
#include <cuda_bf16.h>
#include <cstdint>

// ---------------- problem constants ----------------
#define C_CLS   201
#define K_PROT  5
#define DIM     768
#define B_IMG   64
#define NP      256
#define BN_TOT  16384
#define CK      1005
#define NPAD    1024
#define KSPLIT  2304          // 3 * 768 (Ah|Ah|Al vs Bh|Bl|Bh)
#define EPSV    1e-12f

#define SZ_PP   (BN_TOT*CK)
#define SZ_IMG  (B_IMG*CK)
#define SZ_CLS  (B_IMG*(C_CLS-1))
#define SZ_PART (BN_TOT)
#define SZ_NP   (C_CLS*K_PROT*DIM)

// ---------------- device scratch ----------------
__device__ __nv_bfloat16 g_Abf[(size_t)BN_TOT*KSPLIT];   // 75.5 MB
__device__ __nv_bfloat16 g_Bbf[(size_t)NPAD*KSPLIT];     // 4.7 MB
__device__ float g_invA[BN_TOT];
__device__ int   g_rowlist[C_CLS*BN_TOT];
__device__ int   g_count[C_CLS];
__device__ float g_Q[BN_TOT*K_PROT];
__device__ float g_Pacc[SZ_NP];
__device__ int   g_wl[1024];          // packed (class<<16)|chunk
__device__ int   g_nw;

__device__ __forceinline__ uint32_t smem_u32(const void* p) {
    uint32_t a;
    asm("{ .reg .u64 t; cvta.to.shared.u64 t, %1; cvt.u32.u64 %0, t; }" : "=r"(a) : "l"(p));
    return a;
}

// ---------------- kernel 0: zero scratch ----------------
__global__ void zero_k() {
    int i = blockIdx.x * 256 + threadIdx.x;
    if (i < SZ_NP)  g_Pacc[i] = 0.0f;
    if (i < C_CLS)  g_count[i] = 0;
}

// ---------------- conv: normalize + bf16 hi/lo split ----------------
// A' cols: [hi | hi | lo]   B' cols: [hi | lo | hi]
template <int MODE>   // 0: tokens -> g_Abf (+g_invA); 1: protos -> g_Bbf
__global__ void __launch_bounds__(256) conv_k(const float* __restrict__ in, int nrows) {
    int row = blockIdx.x;
    int tid = threadIdx.x;
    __shared__ float red[8];
    __nv_bfloat16* dst = (MODE == 0 ? g_Abf : g_Bbf) + (size_t)row * KSPLIT;

    if (MODE == 1 && row >= nrows) {
        __nv_bfloat16 z = __float2bfloat16(0.0f);
        for (int i = tid; i < KSPLIT; i += 256) dst[i] = z;
        return;
    }
    const float* rp = in + (size_t)row * DIM;
    float v[3]; float s = 0.0f;
#pragma unroll
    for (int i = 0; i < 3; i++) { v[i] = rp[tid + i*256]; s += v[i]*v[i]; }
#pragma unroll
    for (int o = 16; o; o >>= 1) s += __shfl_xor_sync(0xffffffffu, s, o);
    if ((tid & 31) == 0) red[tid >> 5] = s;
    __syncthreads();
    float tot = 0.0f;
#pragma unroll
    for (int w = 0; w < 8; w++) tot += red[w];
    float inv = 1.0f / (sqrtf(tot) + EPSV);
    if (MODE == 0 && tid == 0) g_invA[row] = inv;
#pragma unroll
    for (int i = 0; i < 3; i++) {
        float a = v[i] * inv;
        __nv_bfloat16 hi = __float2bfloat16(a);
        __nv_bfloat16 lo = __float2bfloat16(a - __bfloat162float(hi));
        int c = tid + i*256;
        if (MODE == 0) {
            dst[c] = hi; dst[768 + c] = hi; dst[1536 + c] = lo;
        } else {
            dst[c] = hi; dst[768 + c] = lo; dst[1536 + c] = hi;
        }
    }
}

// ---------------- GEMM: mma.sync bf16, CTA 128x128, 4 warps 64x64, cp.async x4 ----------------
#define NSTAGE  72              // 2304/32
#define STAGES  4
#define STG_BYTES 20480         // (128*40 A + 128*40 B) bf16 = 2*10240 B

__device__ __forceinline__ void ldsm4(uint32_t& r0, uint32_t& r1, uint32_t& r2, uint32_t& r3,
                                      uint32_t addr) {
    asm volatile("ldmatrix.sync.aligned.m8n8.x4.shared.b16 {%0,%1,%2,%3}, [%4];"
                 : "=r"(r0), "=r"(r1), "=r"(r2), "=r"(r3) : "r"(addr));
}
__device__ __forceinline__ void mma16816(float* c, const uint32_t* a, const uint32_t* b) {
    asm volatile("mma.sync.aligned.m16n8k16.row.col.f32.bf16.bf16.f32 "
                 "{%0,%1,%2,%3}, {%4,%5,%6,%7}, {%8,%9}, {%0,%1,%2,%3};"
                 : "+f"(c[0]), "+f"(c[1]), "+f"(c[2]), "+f"(c[3])
                 : "r"(a[0]), "r"(a[1]), "r"(a[2]), "r"(a[3]), "r"(b[0]), "r"(b[1]));
}
__device__ __forceinline__ void cpa16(uint32_t dst, const void* src) {
    asm volatile("cp.async.cg.shared.global [%0], [%1], 16;" :: "r"(dst), "l"(src));
}

__global__ void __launch_bounds__(128, 2) gemm_mma(float* __restrict__ Cout) {
    extern __shared__ char sm[];

    int tid = threadIdx.x;
    int lane = tid & 31;
    int warp = tid >> 5;
    int wm = warp & 1;            // m offset 64*wm
    int wn = warp >> 1;           // n offset 64*wn
    int row0 = blockIdx.y * 128;
    int col0 = blockIdx.x * 128;

    uint32_t sbase = smem_u32(sm);
    const char* gA = (const char*)g_Abf + (size_t)(row0 + tid) * (KSPLIT*2);
    const char* gB = (const char*)g_Bbf + (size_t)(col0 + tid) * (KSPLIT*2);

    uint32_t a_lane = (uint32_t)((((lane >> 3) & 1)*8 + (lane & 7))*80 + ((lane >> 4) & 1)*16);
    uint32_t b_lane = (uint32_t)((((lane >> 4) & 1)*8 + (lane & 7))*80 + ((lane >> 3) & 1)*16);
    uint32_t a_off = (uint32_t)(wm*64)*80 + a_lane;
    uint32_t b_off = 10240u + (uint32_t)(wn*64)*80 + b_lane;

    float acc[4][8][4];
#pragma unroll
    for (int i = 0; i < 4; i++)
#pragma unroll
        for (int j = 0; j < 8; j++)
#pragma unroll
            for (int r = 0; r < 4; r++) acc[i][j][r] = 0.0f;

    // prologue: issue stages 0..2
#pragma unroll
    for (int p = 0; p < STAGES - 1; p++) {
        uint32_t dA = sbase + p*STG_BYTES + tid*80;
        const char* pA = gA + p*64;
        const char* pB = gB + p*64;
#pragma unroll
        for (int c = 0; c < 4; c++) {
            cpa16(dA + c*16, pA + c*16);
            cpa16(dA + 10240 + c*16, pB + c*16);
        }
        asm volatile("cp.async.commit_group;" ::: "memory");
    }

    for (int s = 0; s < NSTAGE; s++) {
        asm volatile("cp.async.wait_group 2;" ::: "memory");
        __syncthreads();
        uint32_t stg = sbase + (uint32_t)(s & 3)*STG_BYTES;
        uint32_t ab = stg + a_off;
        uint32_t bb = stg + b_off;
#pragma unroll
        for (int ks = 0; ks < 2; ks++) {
            uint32_t af[4][4], bf[4][4];
#pragma unroll
            for (int i = 0; i < 4; i++)
                ldsm4(af[i][0], af[i][1], af[i][2], af[i][3], ab + ks*32 + i*16*80);
#pragma unroll
            for (int j = 0; j < 4; j++)
                ldsm4(bf[j][0], bf[j][1], bf[j][2], bf[j][3], bb + ks*32 + j*16*80);
#pragma unroll
            for (int im = 0; im < 4; im++)
#pragma unroll
                for (int j = 0; j < 4; j++) {
                    mma16816(acc[im][2*j],   af[im], &bf[j][0]);
                    mma16816(acc[im][2*j+1], af[im], &bf[j][2]);
                }
        }
        if (s + STAGES - 1 < NSTAGE) {
            int p = s + STAGES - 1;
            uint32_t dA = sbase + (uint32_t)(p & 3)*STG_BYTES + tid*80;
            const char* pA = gA + p*64;
            const char* pB = gB + p*64;
#pragma unroll
            for (int c = 0; c < 4; c++) {
                cpa16(dA + c*16, pA + c*16);
                cpa16(dA + 10240 + c*16, pB + c*16);
            }
        }
        asm volatile("cp.async.commit_group;" ::: "memory");
    }

    // epilogue: scalar stores (CK=1005 odd -> rows not 8B aligned)
    int mb = row0 + wm*64 + (lane >> 2);
    int nb0 = col0 + wn*64 + (lane & 3)*2;
#pragma unroll
    for (int im = 0; im < 4; im++) {
        size_t r0 = (size_t)(mb + im*16) * CK;
        size_t r1 = (size_t)(mb + im*16 + 8) * CK;
#pragma unroll
        for (int j = 0; j < 8; j++) {
            int n = nb0 + j*8;
            if (n < CK) {
                Cout[r0 + n] = acc[im][j][0];
                Cout[r1 + n] = acc[im][j][2];
            }
            if (n + 1 < CK) {
                Cout[r0 + n + 1] = acc[im][j][1];
                Cout[r1 + n + 1] = acc[im][j][3];
            }
        }
    }
}

// ---------------- mean over patches ----------------
__global__ void mean_img(const float* __restrict__ L, float* __restrict__ img) {
    int ck = blockIdx.x * 256 + threadIdx.x;
    int b = blockIdx.y;
    if (ck >= CK) return;
    const float* base = L + (size_t)b * NP * CK + ck;
    float s = 0.0f;
    for (int n = 0; n < NP; n++) s += base[(size_t)n * CK];
    img[b*CK + ck] = s * (1.0f/256.0f);
}

// ---------------- class logits ----------------
__global__ void cls_logits(const float* __restrict__ img, const float* __restrict__ sa,
                           const float* __restrict__ scale_p, float* __restrict__ out) {
    int idx = blockIdx.x * 256 + threadIdx.x;
    if (idx >= SZ_CLS) return;
    int b = idx / (C_CLS-1), c = idx % (C_CLS-1);
    float s[K_PROT], mx = -1e30f;
#pragma unroll
    for (int k = 0; k < K_PROT; k++) { s[k] = sa[c*K_PROT + k]; mx = fmaxf(mx, s[k]); }
    float den = 0.0f;
#pragma unroll
    for (int k = 0; k < K_PROT; k++) { s[k] = expf(s[k] - mx); den += s[k]; }
    float scale = scale_p[0];
    float acc = 0.0f;
#pragma unroll
    for (int k = 0; k < K_PROT; k++)
        acc += scale * img[b*CK + c*K_PROT + k] * (s[k] / den * (float)K_PROT);
    out[idx] = acc;
}

// ---------------- pseudo labels + per-class row lists ----------------
__global__ void pseudo_k(const int* __restrict__ labels, const unsigned* __restrict__ masks,
                         float* __restrict__ out_pl) {
    int bn = blockIdx.x * 256 + threadIdx.x;
    int b = bn >> 8;
    int lab = labels[b];
    int pl = (masks[bn] != 0u) ? lab : (C_CLS - 1);
    out_pl[bn] = (float)pl;
    int pos = atomicAdd(&g_count[pl], 1);
    g_rowlist[pl*BN_TOT + pos] = bn;
}

// ---------------- worklist: compact (class, chunk) pairs ----------------
#define PR 64
__global__ void worklist_k() {
    __shared__ int sc[256];
    int tid = threadIdx.x;
    int n = (tid < C_CLS) ? (g_count[tid] + PR - 1) / PR : 0;
    sc[tid] = n;
    __syncthreads();
    for (int off = 1; off < 256; off <<= 1) {
        int v = (tid >= off) ? sc[tid - off] : 0;
        __syncthreads();
        sc[tid] += v;
        __syncthreads();
    }
    int end = sc[tid];
    int start = end - n;
    for (int i = 0; i < n; i++) g_wl[start + i] = (tid << 16) | i;
    if (tid == 255) g_nw = sc[255];
}

// ---------------- per-class masked Sinkhorn + argmax ----------------
__global__ void __launch_bounds__(512) sinkhorn_k(const float* __restrict__ L,
                                                  float* __restrict__ out_part) {
    int c = blockIdx.x;
    int M = g_count[c];
    if (M == 0) return;
    int tid = threadIdx.x;
    int lane = tid & 31;
    __shared__ float s_col[K_PROT];
    const int* rl = g_rowlist + c*BN_TOT;

    float ps[K_PROT];
#pragma unroll
    for (int k = 0; k < K_PROT; k++) ps[k] = 0.0f;

    for (int r = tid; r < M; r += 512) {
        int n = rl[r];
        const float* lp = L + (size_t)n*CK + c*K_PROT;
        float q[K_PROT], mx = lp[0];
#pragma unroll
        for (int k = 0; k < K_PROT; k++) { q[k] = lp[k]; mx = fmaxf(mx, q[k]); }
        float den = 0.0f;
#pragma unroll
        for (int k = 0; k < K_PROT; k++) { q[k] = expf(q[k] - mx); den += q[k]; }
#pragma unroll
        for (int k = 0; k < K_PROT; k++) {
            q[k] = q[k] / den;
            g_Q[n*K_PROT + k] = q[k];
            ps[k] += q[k];
        }
    }

    for (int it = 0; it < 3; it++) {
        __syncthreads();
        if (tid < K_PROT) s_col[tid] = 0.0f;
        __syncthreads();
#pragma unroll
        for (int k = 0; k < K_PROT; k++) {
            float v = ps[k];
#pragma unroll
            for (int o = 16; o; o >>= 1) v += __shfl_xor_sync(0xffffffffu, v, o);
            if (lane == 0) atomicAdd(&s_col[k], v);
        }
        __syncthreads();
        float sc[K_PROT];
#pragma unroll
        for (int k = 0; k < K_PROT; k++) sc[k] = s_col[k] + EPSV;

        float nps[K_PROT];
#pragma unroll
        for (int k = 0; k < K_PROT; k++) nps[k] = 0.0f;

        for (int r = tid; r < M; r += 512) {
            int n = rl[r];
            float q[K_PROT], rs = 0.0f;
#pragma unroll
            for (int k = 0; k < K_PROT; k++) {
                q[k] = g_Q[n*K_PROT + k] / sc[k];
                rs += q[k];
            }
            rs += EPSV;
#pragma unroll
            for (int k = 0; k < K_PROT; k++) {
                q[k] = q[k] / rs;
                g_Q[n*K_PROT + k] = q[k];
                nps[k] += q[k];
            }
            if (it == 2) {
                float best = q[0]; int bi = 0;
#pragma unroll
                for (int k = 1; k < K_PROT; k++)
                    if (q[k] > best) { best = q[k]; bi = k; }
                out_part[n] = (float)bi;
            }
        }
#pragma unroll
        for (int k = 0; k < K_PROT; k++) ps[k] = nps[k];
    }
}

// ---------------- prototype candidates (worklist-driven) ----------------
__global__ void __launch_bounds__(256) pnew_k(const float* __restrict__ tok) {
    if (blockIdx.x >= g_nw) return;
    int w = g_wl[blockIdx.x];
    int c = w >> 16;
    int start = (w & 0xffff) * PR;
    int M = g_count[c];
    int nr = min(PR, M - start);
    int tid = threadIdx.x;
    __shared__ int   rn[PR];
    __shared__ float qs[PR*K_PROT];

    if (tid < nr) rn[tid] = g_rowlist[c*BN_TOT + start + tid];
    __syncthreads();
    for (int i = tid; i < nr*K_PROT; i += 256) {
        int n = rn[i / K_PROT];
        qs[i] = g_Q[n*K_PROT + (i % K_PROT)] * g_invA[n];
    }
    __syncthreads();

    float acc[3][K_PROT];
#pragma unroll
    for (int j = 0; j < 3; j++)
#pragma unroll
        for (int k = 0; k < K_PROT; k++) acc[j][k] = 0.0f;

    const float* tp = tok + (size_t)rn[0]*DIM;
    float a0 = tp[tid], a1 = tp[tid+256], a2 = tp[tid+512];
    for (int r = 0; r < nr; r++) {
        float b0 = 0.f, b1 = 0.f, b2 = 0.f;
        if (r + 1 < nr) {
            const float* tq = tok + (size_t)rn[r+1]*DIM;
            b0 = tq[tid]; b1 = tq[tid+256]; b2 = tq[tid+512];
        }
#pragma unroll
        for (int k = 0; k < K_PROT; k++) {
            float q = qs[r*K_PROT + k];
            acc[0][k] += q * a0;
            acc[1][k] += q * a1;
            acc[2][k] += q * a2;
        }
        a0 = b0; a1 = b1; a2 = b2;
    }
    float* P = g_Pacc + (size_t)c * (K_PROT*DIM);
#pragma unroll
    for (int k = 0; k < K_PROT; k++)
#pragma unroll
        for (int j = 0; j < 3; j++)
            atomicAdd(&P[k*DIM + tid + j*256], acc[j][k]);
}

// ---------------- EMA prototype update ----------------
__global__ void combine_k(const float* __restrict__ proto, float* __restrict__ out_np) {
    int i = blockIdx.x * 256 + threadIdx.x;
    if (i >= SZ_NP) return;
    int c = i / (K_PROT*DIM);
    float p = proto[i];
    out_np[i] = (g_count[c] > 0) ? 0.999f*p + 0.001f*g_Pacc[i] : p;
}

// ---------------- launch ----------------
extern "C" void kernel_launch(void* const* d_in, const int* in_sizes, int n_in,
                              void* d_out, int out_size) {
    const float*    tok    = (const float*)d_in[0];
    const float*    proto  = (const float*)d_in[1];
    const float*    sa     = (const float*)d_in[2];
    const float*    scale  = (const float*)d_in[3];
    const int*      labels = (const int*)d_in[4];
    const unsigned* masks  = (const unsigned*)d_in[5];

    float* out      = (float*)d_out;
    float* out_pp   = out;
    float* out_img  = out_pp  + SZ_PP;
    float* out_cls  = out_img + SZ_IMG;
    float* out_part = out_cls + SZ_CLS;
    float* out_np   = out_part + SZ_PART;
    float* out_pl   = out_np  + SZ_NP;

    const int GEMM_SMEM = STAGES * STG_BYTES;   // 81920
    cudaFuncSetAttribute(gemm_mma, cudaFuncAttributeMaxDynamicSharedMemorySize, GEMM_SMEM);

    zero_k<<<(SZ_NP + 255)/256, 256>>>();
    conv_k<0><<<BN_TOT, 256>>>(tok, BN_TOT);
    conv_k<1><<<NPAD, 256>>>(proto, CK);
    {
        dim3 grid(NPAD/128, BN_TOT/128);   // (8, 128)
        gemm_mma<<<grid, 128, GEMM_SMEM>>>(out_pp);
    }
    {
        dim3 grid((CK + 255)/256, B_IMG);
        mean_img<<<grid, 256>>>(out_pp, out_img);
    }
    cls_logits<<<(SZ_CLS + 255)/256, 256>>>(out_img, sa, scale, out_cls);
    pseudo_k<<<BN_TOT/256, 256>>>(labels, masks, out_pl);
    worklist_k<<<1, 256>>>();
    sinkhorn_k<<<C_CLS, 512>>>(out_pp, out_part);
    pnew_k<<<512, 256>>>(tok);
    combine_k<<<(SZ_NP + 255)/256, 256>>>(proto, out_np);
}

// round 8
// speedup vs baseline: 1.8407x; 1.0300x over previous
#include <cuda_runtime.h>
#include <cuda_bf16.h>
#include <cstdint>

// ---------------- problem constants ----------------
#define C_CLS   201
#define K_PROT  5
#define DIM     768
#define B_IMG   64
#define NP      256
#define BN_TOT  16384
#define CK      1005
#define NPAD    1024
#define KSPLIT  1536          // stored [hi | lo]; logical K = 2304 via chunk remap
#define EPSV    1e-12f

#define SZ_PP   (BN_TOT*CK)
#define SZ_IMG  (B_IMG*CK)
#define SZ_CLS  (B_IMG*(C_CLS-1))
#define SZ_PART (BN_TOT)
#define SZ_NP   (C_CLS*K_PROT*DIM)

// ---------------- device scratch ----------------
__device__ __nv_bfloat16 g_Abf[(size_t)BN_TOT*KSPLIT];   // 50.3 MB
__device__ __nv_bfloat16 g_Bbf[(size_t)NPAD*KSPLIT];     // 3.1 MB
__device__ float g_invA[BN_TOT];
__device__ int   g_rowlist[C_CLS*BN_TOT];
__device__ int   g_count[C_CLS];
__device__ float g_Q[BN_TOT*K_PROT];
__device__ float g_Pacc[SZ_NP];
__device__ float g_part[128*1024];    // per row-block column sums
__device__ int   g_wl[1024];          // packed (class<<16)|chunk
__device__ int   g_nw;

__device__ __forceinline__ uint32_t smem_u32(const void* p) {
    uint32_t a;
    asm("{ .reg .u64 t; cvta.to.shared.u64 t, %1; cvt.u32.u64 %0, t; }" : "=r"(a) : "l"(p));
    return a;
}

// ---------------- kernel 0: zero scratch ----------------
__global__ void zero_k() {
    int i = blockIdx.x * 256 + threadIdx.x;
    if (i < SZ_NP)  g_Pacc[i] = 0.0f;
    if (i < C_CLS)  g_count[i] = 0;
}

// ---------------- conv: normalize + bf16 hi/lo split, stored [hi|lo] ----------------
template <int MODE>   // 0: tokens -> g_Abf (+g_invA); 1: protos -> g_Bbf
__global__ void __launch_bounds__(256) conv_k(const float* __restrict__ in, int nrows) {
    int row = blockIdx.x;
    int tid = threadIdx.x;
    __shared__ float red[8];
    __nv_bfloat16* dst = (MODE == 0 ? g_Abf : g_Bbf) + (size_t)row * KSPLIT;

    if (MODE == 1 && row >= nrows) {
        __nv_bfloat16 z = __float2bfloat16(0.0f);
        for (int i = tid; i < KSPLIT; i += 256) dst[i] = z;
        return;
    }
    const float* rp = in + (size_t)row * DIM;
    float v[3]; float s = 0.0f;
#pragma unroll
    for (int i = 0; i < 3; i++) { v[i] = rp[tid + i*256]; s += v[i]*v[i]; }
#pragma unroll
    for (int o = 16; o; o >>= 1) s += __shfl_xor_sync(0xffffffffu, s, o);
    if ((tid & 31) == 0) red[tid >> 5] = s;
    __syncthreads();
    float tot = 0.0f;
#pragma unroll
    for (int w = 0; w < 8; w++) tot += red[w];
    float inv = 1.0f / (sqrtf(tot) + EPSV);
    if (MODE == 0 && tid == 0) g_invA[row] = inv;
#pragma unroll
    for (int i = 0; i < 3; i++) {
        float a = v[i] * inv;
        __nv_bfloat16 hi = __float2bfloat16(a);
        __nv_bfloat16 lo = __float2bfloat16(a - __bfloat162float(hi));
        int c = tid + i*256;
        dst[c] = hi; dst[768 + c] = lo;
    }
}

// ---------------- GEMM: mma.sync bf16, CTA 128x128, logical K=2304 ----------------
// logical chunks s=0..71 (32 cols each): A' = [Ah|Ah|Al], B' = [Bh|Bl|Bh]
// physical: A chunk = s<24 ? s : s-24 ; B chunk = s<48 ? s : s-48
#define NSTAGE  72
#define STAGES  4
#define STG_BYTES 20480

__device__ __forceinline__ void ldsm4(uint32_t& r0, uint32_t& r1, uint32_t& r2, uint32_t& r3,
                                      uint32_t addr) {
    asm volatile("ldmatrix.sync.aligned.m8n8.x4.shared.b16 {%0,%1,%2,%3}, [%4];"
                 : "=r"(r0), "=r"(r1), "=r"(r2), "=r"(r3) : "r"(addr));
}
__device__ __forceinline__ void mma16816(float* c, const uint32_t* a, const uint32_t* b) {
    asm volatile("mma.sync.aligned.m16n8k16.row.col.f32.bf16.bf16.f32 "
                 "{%0,%1,%2,%3}, {%4,%5,%6,%7}, {%8,%9}, {%0,%1,%2,%3};"
                 : "+f"(c[0]), "+f"(c[1]), "+f"(c[2]), "+f"(c[3])
                 : "r"(a[0]), "r"(a[1]), "r"(a[2]), "r"(a[3]), "r"(b[0]), "r"(b[1]));
}
__device__ __forceinline__ void cpa16(uint32_t dst, const void* src) {
    asm volatile("cp.async.cg.shared.global [%0], [%1], 16;" :: "r"(dst), "l"(src));
}

__global__ void __launch_bounds__(128, 2) gemm_mma(float* __restrict__ Cout) {
    extern __shared__ char sm[];

    int tid = threadIdx.x;
    int lane = tid & 31;
    int warp = tid >> 5;
    int wm = warp & 1;            // m offset 64*wm
    int wn = warp >> 1;           // n offset 64*wn
    int row0 = blockIdx.y * 128;
    int col0 = blockIdx.x * 128;

    uint32_t sbase = smem_u32(sm);
    const char* gA = (const char*)g_Abf + (size_t)(row0 + tid) * (KSPLIT*2);
    const char* gB = (const char*)g_Bbf + (size_t)(col0 + tid) * (KSPLIT*2);

    uint32_t a_lane = (uint32_t)((((lane >> 3) & 1)*8 + (lane & 7))*80 + ((lane >> 4) & 1)*16);
    uint32_t b_lane = (uint32_t)((((lane >> 4) & 1)*8 + (lane & 7))*80 + ((lane >> 3) & 1)*16);
    uint32_t a_off = (uint32_t)(wm*64)*80 + a_lane;
    uint32_t b_off = 10240u + (uint32_t)(wn*64)*80 + b_lane;

    float acc[4][8][4];
#pragma unroll
    for (int i = 0; i < 4; i++)
#pragma unroll
        for (int j = 0; j < 8; j++)
#pragma unroll
            for (int r = 0; r < 4; r++) acc[i][j][r] = 0.0f;

    // prologue: issue stages 0..2 (identity chunk map for p<24)
#pragma unroll
    for (int p = 0; p < STAGES - 1; p++) {
        uint32_t dA = sbase + p*STG_BYTES + tid*80;
        const char* pA = gA + p*64;
        const char* pB = gB + p*64;
#pragma unroll
        for (int c = 0; c < 4; c++) {
            cpa16(dA + c*16, pA + c*16);
            cpa16(dA + 10240 + c*16, pB + c*16);
        }
        asm volatile("cp.async.commit_group;" ::: "memory");
    }

    for (int s = 0; s < NSTAGE; s++) {
        asm volatile("cp.async.wait_group 2;" ::: "memory");
        __syncthreads();
        uint32_t stg = sbase + (uint32_t)(s & 3)*STG_BYTES;
        uint32_t ab = stg + a_off;
        uint32_t bb = stg + b_off;
#pragma unroll
        for (int ks = 0; ks < 2; ks++) {
            uint32_t af[4][4], bf[4][4];
#pragma unroll
            for (int i = 0; i < 4; i++)
                ldsm4(af[i][0], af[i][1], af[i][2], af[i][3], ab + ks*32 + i*16*80);
#pragma unroll
            for (int j = 0; j < 4; j++)
                ldsm4(bf[j][0], bf[j][1], bf[j][2], bf[j][3], bb + ks*32 + j*16*80);
#pragma unroll
            for (int im = 0; im < 4; im++)
#pragma unroll
                for (int j = 0; j < 4; j++) {
                    mma16816(acc[im][2*j],   af[im], &bf[j][0]);
                    mma16816(acc[im][2*j+1], af[im], &bf[j][2]);
                }
        }
        if (s + STAGES - 1 < NSTAGE) {
            int p = s + STAGES - 1;
            int pa = (p < 24) ? p : (p - 24);     // A: [Ah|Ah|Al] -> [hi|lo]
            int pb = (p < 48) ? p : (p - 48);     // B: [Bh|Bl|Bh] -> [hi|lo]
            uint32_t dA = sbase + (uint32_t)(p & 3)*STG_BYTES + tid*80;
            const char* pA = gA + pa*64;
            const char* pB = gB + pb*64;
#pragma unroll
            for (int c = 0; c < 4; c++) {
                cpa16(dA + c*16, pA + c*16);
                cpa16(dA + 10240 + c*16, pB + c*16);
            }
        }
        asm volatile("cp.async.commit_group;" ::: "memory");
    }

    // ----- fused patch-mean partials: column sums over this CTA's 128 rows -----
    float cs[16];
#pragma unroll
    for (int j = 0; j < 8; j++)
#pragma unroll
        for (int h = 0; h < 2; h++) {
            float v = 0.0f;
#pragma unroll
            for (int im = 0; im < 4; im++) v += acc[im][j][h] + acc[im][j][h+2];
            cs[j*2+h] = v;
        }
#pragma unroll
    for (int o = 4; o <= 16; o <<= 1)
#pragma unroll
        for (int t = 0; t < 16; t++) cs[t] += __shfl_xor_sync(0xffffffffu, cs[t], o);

    __syncthreads();   // all MMA + cp.async done; reuse smem
    float* scol = (float*)sm;          // [2][128]
    if (lane < 4) {
#pragma unroll
        for (int j = 0; j < 8; j++) {
            scol[wm*128 + wn*64 + lane*2 + j*8]     = cs[j*2];
            scol[wm*128 + wn*64 + lane*2 + j*8 + 1] = cs[j*2+1];
        }
    }
    __syncthreads();
    if (tid < 128)
        g_part[blockIdx.y*1024 + col0 + tid] = scol[tid] + scol[128 + tid];

    // epilogue: scalar stores (CK=1005 odd -> rows not 8B aligned)
    int mb = row0 + wm*64 + (lane >> 2);
    int nb0 = col0 + wn*64 + (lane & 3)*2;
#pragma unroll
    for (int im = 0; im < 4; im++) {
        size_t r0 = (size_t)(mb + im*16) * CK;
        size_t r1 = (size_t)(mb + im*16 + 8) * CK;
#pragma unroll
        for (int j = 0; j < 8; j++) {
            int n = nb0 + j*8;
            if (n < CK) {
                Cout[r0 + n] = acc[im][j][0];
                Cout[r1 + n] = acc[im][j][2];
            }
            if (n + 1 < CK) {
                Cout[r0 + n + 1] = acc[im][j][1];
                Cout[r1 + n + 1] = acc[im][j][3];
            }
        }
    }
}

// ---------------- combine partial sums -> image logits ----------------
__global__ void mean2(float* __restrict__ img) {
    int idx = blockIdx.x * 256 + threadIdx.x;
    if (idx >= SZ_IMG) return;
    int b = idx / CK, ck = idx % CK;
    img[idx] = (g_part[(2*b)*1024 + ck] + g_part[(2*b+1)*1024 + ck]) * (1.0f/256.0f);
}

// ---------------- class logits ----------------
__global__ void cls_logits(const float* __restrict__ img, const float* __restrict__ sa,
                           const float* __restrict__ scale_p, float* __restrict__ out) {
    int idx = blockIdx.x * 256 + threadIdx.x;
    if (idx >= SZ_CLS) return;
    int b = idx / (C_CLS-1), c = idx % (C_CLS-1);
    float s[K_PROT], mx = -1e30f;
#pragma unroll
    for (int k = 0; k < K_PROT; k++) { s[k] = sa[c*K_PROT + k]; mx = fmaxf(mx, s[k]); }
    float den = 0.0f;
#pragma unroll
    for (int k = 0; k < K_PROT; k++) { s[k] = expf(s[k] - mx); den += s[k]; }
    float scale = scale_p[0];
    float acc = 0.0f;
#pragma unroll
    for (int k = 0; k < K_PROT; k++)
        acc += scale * img[b*CK + c*K_PROT + k] * (s[k] / den * (float)K_PROT);
    out[idx] = acc;
}

// ---------------- pseudo labels + per-class row lists ----------------
__global__ void pseudo_k(const int* __restrict__ labels, const unsigned* __restrict__ masks,
                         float* __restrict__ out_pl) {
    int bn = blockIdx.x * 256 + threadIdx.x;
    int b = bn >> 8;
    int lab = labels[b];
    int pl = (masks[bn] != 0u) ? lab : (C_CLS - 1);
    out_pl[bn] = (float)pl;
    int pos = atomicAdd(&g_count[pl], 1);
    g_rowlist[pl*BN_TOT + pos] = bn;
}

// ---------------- worklist: compact (class, chunk) pairs ----------------
#define PR 32
__global__ void worklist_k() {
    __shared__ int sc[256];
    int tid = threadIdx.x;
    int n = (tid < C_CLS) ? (g_count[tid] + PR - 1) / PR : 0;
    sc[tid] = n;
    __syncthreads();
    for (int off = 1; off < 256; off <<= 1) {
        int v = (tid >= off) ? sc[tid - off] : 0;
        __syncthreads();
        sc[tid] += v;
        __syncthreads();
    }
    int end = sc[tid];
    int start = end - n;
    for (int i = 0; i < n; i++) g_wl[start + i] = (tid << 16) | i;
    if (tid == 255) g_nw = sc[255];
}

// ---------------- per-class masked Sinkhorn + argmax ----------------
__global__ void __launch_bounds__(1024) sinkhorn_k(const float* __restrict__ L,
                                                   float* __restrict__ out_part) {
    int c = blockIdx.x;
    int M = g_count[c];
    if (M == 0) return;
    int tid = threadIdx.x;
    int lane = tid & 31;
    __shared__ float s_col[K_PROT];
    const int* rl = g_rowlist + c*BN_TOT;

    float ps[K_PROT];
#pragma unroll
    for (int k = 0; k < K_PROT; k++) ps[k] = 0.0f;

    for (int r = tid; r < M; r += 1024) {
        int n = rl[r];
        const float* lp = L + (size_t)n*CK + c*K_PROT;
        float q[K_PROT], mx = lp[0];
#pragma unroll
        for (int k = 0; k < K_PROT; k++) { q[k] = lp[k]; mx = fmaxf(mx, q[k]); }
        float den = 0.0f;
#pragma unroll
        for (int k = 0; k < K_PROT; k++) { q[k] = expf(q[k] - mx); den += q[k]; }
#pragma unroll
        for (int k = 0; k < K_PROT; k++) {
            q[k] = q[k] / den;
            g_Q[n*K_PROT + k] = q[k];
            ps[k] += q[k];
        }
    }

    for (int it = 0; it < 3; it++) {
        __syncthreads();
        if (tid < K_PROT) s_col[tid] = 0.0f;
        __syncthreads();
#pragma unroll
        for (int k = 0; k < K_PROT; k++) {
            float v = ps[k];
#pragma unroll
            for (int o = 16; o; o >>= 1) v += __shfl_xor_sync(0xffffffffu, v, o);
            if (lane == 0) atomicAdd(&s_col[k], v);
        }
        __syncthreads();
        float sc[K_PROT];
#pragma unroll
        for (int k = 0; k < K_PROT; k++) sc[k] = s_col[k] + EPSV;

        float nps[K_PROT];
#pragma unroll
        for (int k = 0; k < K_PROT; k++) nps[k] = 0.0f;

        for (int r = tid; r < M; r += 1024) {
            int n = rl[r];
            float q[K_PROT], rs = 0.0f;
#pragma unroll
            for (int k = 0; k < K_PROT; k++) {
                q[k] = g_Q[n*K_PROT + k] / sc[k];
                rs += q[k];
            }
            rs += EPSV;
#pragma unroll
            for (int k = 0; k < K_PROT; k++) {
                q[k] = q[k] / rs;
                g_Q[n*K_PROT + k] = q[k];
                nps[k] += q[k];
            }
            if (it == 2) {
                float best = q[0]; int bi = 0;
#pragma unroll
                for (int k = 1; k < K_PROT; k++)
                    if (q[k] > best) { best = q[k]; bi = k; }
                out_part[n] = (float)bi;
            }
        }
#pragma unroll
        for (int k = 0; k < K_PROT; k++) ps[k] = nps[k];
    }
}

// ---------------- prototype candidates (worklist-driven, 2-deep prefetch) ----------------
__global__ void __launch_bounds__(256) pnew_k(const float* __restrict__ tok) {
    if (blockIdx.x >= g_nw) return;
    int w = g_wl[blockIdx.x];
    int c = w >> 16;
    int start = (w & 0xffff) * PR;
    int M = g_count[c];
    int nr = min(PR, M - start);
    int tid = threadIdx.x;
    __shared__ int   rn[PR];
    __shared__ float qs[PR*K_PROT];

    if (tid < nr) rn[tid] = g_rowlist[c*BN_TOT + start + tid];
    __syncthreads();
    for (int i = tid; i < nr*K_PROT; i += 256) {
        int n = rn[i / K_PROT];
        qs[i] = g_Q[n*K_PROT + (i % K_PROT)] * g_invA[n];
    }
    __syncthreads();

    float acc[3][K_PROT];
#pragma unroll
    for (int j = 0; j < 3; j++)
#pragma unroll
        for (int k = 0; k < K_PROT; k++) acc[j][k] = 0.0f;

    float pf[2][3];
    {
        const float* t0 = tok + (size_t)rn[0]*DIM;
        pf[0][0] = t0[tid]; pf[0][1] = t0[tid+256]; pf[0][2] = t0[tid+512];
    }
    if (nr > 1) {
        const float* t1 = tok + (size_t)rn[1]*DIM;
        pf[1][0] = t1[tid]; pf[1][1] = t1[tid+256]; pf[1][2] = t1[tid+512];
    }
    for (int r = 0; r < nr; r++) {
        float a0 = pf[r&1][0], a1 = pf[r&1][1], a2 = pf[r&1][2];
        if (r + 2 < nr) {
            const float* tq = tok + (size_t)rn[r+2]*DIM;
            pf[r&1][0] = tq[tid]; pf[r&1][1] = tq[tid+256]; pf[r&1][2] = tq[tid+512];
        }
#pragma unroll
        for (int k = 0; k < K_PROT; k++) {
            float q = qs[r*K_PROT + k];
            acc[0][k] += q * a0;
            acc[1][k] += q * a1;
            acc[2][k] += q * a2;
        }
    }
    float* P = g_Pacc + (size_t)c * (K_PROT*DIM);
#pragma unroll
    for (int k = 0; k < K_PROT; k++)
#pragma unroll
        for (int j = 0; j < 3; j++)
            atomicAdd(&P[k*DIM + tid + j*256], acc[j][k]);
}

// ---------------- EMA prototype update ----------------
__global__ void combine_k(const float* __restrict__ proto, float* __restrict__ out_np) {
    int i = blockIdx.x * 256 + threadIdx.x;
    if (i >= SZ_NP) return;
    int c = i / (K_PROT*DIM);
    float p = proto[i];
    out_np[i] = (g_count[c] > 0) ? 0.999f*p + 0.001f*g_Pacc[i] : p;
}

// ---------------- launch ----------------
extern "C" void kernel_launch(void* const* d_in, const int* in_sizes, int n_in,
                              void* d_out, int out_size) {
    const float*    tok    = (const float*)d_in[0];
    const float*    proto  = (const float*)d_in[1];
    const float*    sa     = (const float*)d_in[2];
    const float*    scale  = (const float*)d_in[3];
    const int*      labels = (const int*)d_in[4];
    const unsigned* masks  = (const unsigned*)d_in[5];

    float* out      = (float*)d_out;
    float* out_pp   = out;
    float* out_img  = out_pp  + SZ_PP;
    float* out_cls  = out_img + SZ_IMG;
    float* out_part = out_cls + SZ_CLS;
    float* out_np   = out_part + SZ_PART;
    float* out_pl   = out_np  + SZ_NP;

    const int GEMM_SMEM = STAGES * STG_BYTES;   // 81920
    cudaFuncSetAttribute(gemm_mma, cudaFuncAttributeMaxDynamicSharedMemorySize, GEMM_SMEM);

    zero_k<<<(SZ_NP + 255)/256, 256>>>();
    conv_k<0><<<BN_TOT, 256>>>(tok, BN_TOT);
    conv_k<1><<<NPAD, 256>>>(proto, CK);
    {
        dim3 grid(NPAD/128, BN_TOT/128);   // (8, 128)
        gemm_mma<<<grid, 128, GEMM_SMEM>>>(out_pp);
    }
    mean2<<<(SZ_IMG + 255)/256, 256>>>(out_img);
    cls_logits<<<(SZ_CLS + 255)/256, 256>>>(out_img, sa, scale, out_cls);
    pseudo_k<<<BN_TOT/256, 256>>>(labels, masks, out_pl);
    worklist_k<<<1, 256>>>();
    sinkhorn_k<<<C_CLS, 1024>>>(out_pp, out_part);
    pnew_k<<<768, 256>>>(tok);
    combine_k<<<(SZ_NP + 255)/256, 256>>>(proto, out_np);
}